// round 2
// baseline (speedup 1.0000x reference)
#include <cuda_runtime.h>
#include <cuda_bf16.h>

#define B_DIM 4
#define T_DIM 4096
#define D_DIM 1024
#define HS_DIM 64

#define PITCH 68  // 64 + 4 pad, keeps float4 alignment and odd bank stride

// Scratch for projected K and QV (q == v in this model).
__device__ float g_k[B_DIM * T_DIM * HS_DIM];
__device__ float g_qv[B_DIM * T_DIM * HS_DIM];

// ---------------------------------------------------------------------------
// Projection: k = x @ Wk^T, qv = x @ Wv^T   (x:[16384,1024], W:[64,1024])
// CTA: 64 rows of x, all 64 output cols, both outputs fused (x read once).
// ---------------------------------------------------------------------------
__global__ void proj_kernel(const float* __restrict__ x,
                            const float* __restrict__ Wk,
                            const float* __restrict__ Wv) {
    extern __shared__ float sm[];
    float* sX = sm;                 // [64][PITCH]
    float* sK = sm + 64 * PITCH;    // Wk tile [h][d]
    float* sV = sm + 2 * 64 * PITCH;

    const int tid = threadIdx.x;
    const int tx = tid & 15;        // output col group
    const int ty = tid >> 4;        // output row group
    const int rowBase = blockIdx.x * 64;

    float accK[4][4] = {};
    float accV[4][4] = {};

    for (int d0 = 0; d0 < D_DIM; d0 += 64) {
        __syncthreads();
        #pragma unroll
        for (int l = 0; l < 4; ++l) {
            int idx = tid + l * 256;      // float4 index 0..1023
            int r = idx >> 4;
            int c = (idx & 15) * 4;
            *(float4*)&sX[r * PITCH + c] =
                *(const float4*)&x[(size_t)(rowBase + r) * D_DIM + d0 + c];
            *(float4*)&sK[r * PITCH + c] =
                *(const float4*)&Wk[(size_t)r * D_DIM + d0 + c];
            *(float4*)&sV[r * PITCH + c] =
                *(const float4*)&Wv[(size_t)r * D_DIM + d0 + c];
        }
        __syncthreads();

        #pragma unroll
        for (int d4 = 0; d4 < 16; ++d4) {
            float4 a[4], bk[4], bv[4];
            #pragma unroll
            for (int ii = 0; ii < 4; ++ii)
                a[ii] = *(float4*)&sX[(ty * 4 + ii) * PITCH + d4 * 4];
            #pragma unroll
            for (int hh = 0; hh < 4; ++hh) {
                bk[hh] = *(float4*)&sK[(tx * 4 + hh) * PITCH + d4 * 4];
                bv[hh] = *(float4*)&sV[(tx * 4 + hh) * PITCH + d4 * 4];
            }
            #pragma unroll
            for (int ii = 0; ii < 4; ++ii)
                #pragma unroll
                for (int hh = 0; hh < 4; ++hh) {
                    accK[ii][hh] += a[ii].x * bk[hh].x + a[ii].y * bk[hh].y
                                  + a[ii].z * bk[hh].z + a[ii].w * bk[hh].w;
                    accV[ii][hh] += a[ii].x * bv[hh].x + a[ii].y * bv[hh].y
                                  + a[ii].z * bv[hh].z + a[ii].w * bv[hh].w;
                }
        }
    }

    #pragma unroll
    for (int ii = 0; ii < 4; ++ii) {
        int row = rowBase + ty * 4 + ii;
        float4 vk = make_float4(accK[ii][0], accK[ii][1], accK[ii][2], accK[ii][3]);
        float4 vv = make_float4(accV[ii][0], accV[ii][1], accV[ii][2], accV[ii][3]);
        *(float4*)&g_k[(size_t)row * HS_DIM + tx * 4]  = vk;
        *(float4*)&g_qv[(size_t)row * HS_DIM + tx * 4] = vv;
    }
}

// ---------------------------------------------------------------------------
// Flash attention: out = softmax(qv @ k^T * 0.125, causal) @ qv
// CTA: 64 query rows, one batch. Online softmax, 64-wide key blocks.
// ---------------------------------------------------------------------------
__global__ void attn_kernel(float* __restrict__ out) {
    extern __shared__ float sm[];
    float* sQ = sm;
    float* sK = sm + 64 * PITCH;
    float* sV = sm + 2 * 64 * PITCH;
    float* sP = sm + 3 * 64 * PITCH;

    const int tid = threadIdx.x;
    const int tx = tid & 15;
    const int ty = tid >> 4;
    const int b = blockIdx.y;
    const int mblk = 63 - blockIdx.x;           // longest-running CTAs first
    const int qRow = mblk * 64;

    const float* Kb = g_k  + (size_t)b * T_DIM * HS_DIM;
    const float* Vb = g_qv + (size_t)b * T_DIM * HS_DIM;

    // Load Q tile (Q = qv)
    #pragma unroll
    for (int l = 0; l < 4; ++l) {
        int idx = tid + l * 256;
        int r = idx >> 4;
        int c = (idx & 15) * 4;
        *(float4*)&sQ[r * PITCH + c] =
            *(const float4*)&Vb[(size_t)(qRow + r) * HS_DIM + c];
    }

    float acc[4][4] = {};
    float mrow[4] = {-1e30f, -1e30f, -1e30f, -1e30f};
    float lrow[4] = {0.f, 0.f, 0.f, 0.f};

    for (int kb = 0; kb <= mblk; ++kb) {
        __syncthreads();   // previous PV done before overwriting K/V
        #pragma unroll
        for (int l = 0; l < 4; ++l) {
            int idx = tid + l * 256;
            int r = idx >> 4;
            int c = (idx & 15) * 4;
            *(float4*)&sK[r * PITCH + c] =
                *(const float4*)&Kb[(size_t)(kb * 64 + r) * HS_DIM + c];
            *(float4*)&sV[r * PITCH + c] =
                *(const float4*)&Vb[(size_t)(kb * 64 + r) * HS_DIM + c];
        }
        __syncthreads();

        // S = Q @ K^T (64x64), thread tile 4x4
        float s[4][4] = {};
        #pragma unroll
        for (int h4 = 0; h4 < 16; ++h4) {
            float4 a[4], bb[4];
            #pragma unroll
            for (int ii = 0; ii < 4; ++ii)
                a[ii] = *(float4*)&sQ[(ty * 4 + ii) * PITCH + h4 * 4];
            #pragma unroll
            for (int jj = 0; jj < 4; ++jj)
                bb[jj] = *(float4*)&sK[(tx * 4 + jj) * PITCH + h4 * 4];
            #pragma unroll
            for (int ii = 0; ii < 4; ++ii)
                #pragma unroll
                for (int jj = 0; jj < 4; ++jj)
                    s[ii][jj] += a[ii].x * bb[jj].x + a[ii].y * bb[jj].y
                               + a[ii].z * bb[jj].z + a[ii].w * bb[jj].w;
        }

        // scale + causal mask (only the diagonal block needs masking)
        const bool diag = (kb == mblk);
        #pragma unroll
        for (int ii = 0; ii < 4; ++ii)
            #pragma unroll
            for (int jj = 0; jj < 4; ++jj) {
                float v = s[ii][jj] * 0.125f;
                if (diag && (tx * 4 + jj > ty * 4 + ii)) v = -1e30f;
                s[ii][jj] = v;
            }

        // online softmax per row (16 threads per row, shfl width 16)
        #pragma unroll
        for (int ii = 0; ii < 4; ++ii) {
            float mx = fmaxf(fmaxf(s[ii][0], s[ii][1]), fmaxf(s[ii][2], s[ii][3]));
            #pragma unroll
            for (int off = 8; off > 0; off >>= 1)
                mx = fmaxf(mx, __shfl_xor_sync(0xffffffffu, mx, off, 16));
            float mnew = fmaxf(mrow[ii], mx);
            float corr = __expf(mrow[ii] - mnew);
            float psum = 0.f;
            #pragma unroll
            for (int jj = 0; jj < 4; ++jj) {
                float p = __expf(s[ii][jj] - mnew);
                s[ii][jj] = p;
                psum += p;
            }
            #pragma unroll
            for (int off = 8; off > 0; off >>= 1)
                psum += __shfl_xor_sync(0xffffffffu, psum, off, 16);
            lrow[ii] = lrow[ii] * corr + psum;
            mrow[ii] = mnew;
            #pragma unroll
            for (int cc = 0; cc < 4; ++cc) acc[ii][cc] *= corr;
        }

        // stage P to smem
        #pragma unroll
        for (int ii = 0; ii < 4; ++ii) {
            float4 pv = make_float4(s[ii][0], s[ii][1], s[ii][2], s[ii][3]);
            *(float4*)&sP[(ty * 4 + ii) * PITCH + tx * 4] = pv;
        }
        __syncthreads();

        // O += P @ V
        #pragma unroll
        for (int k4 = 0; k4 < 16; ++k4) {
            float4 p[4];
            #pragma unroll
            for (int ii = 0; ii < 4; ++ii)
                p[ii] = *(float4*)&sP[(ty * 4 + ii) * PITCH + k4 * 4];
            float4 v0 = *(float4*)&sV[(k4 * 4 + 0) * PITCH + tx * 4];
            float4 v1 = *(float4*)&sV[(k4 * 4 + 1) * PITCH + tx * 4];
            float4 v2 = *(float4*)&sV[(k4 * 4 + 2) * PITCH + tx * 4];
            float4 v3 = *(float4*)&sV[(k4 * 4 + 3) * PITCH + tx * 4];
            #pragma unroll
            for (int ii = 0; ii < 4; ++ii) {
                acc[ii][0] += p[ii].x * v0.x + p[ii].y * v1.x + p[ii].z * v2.x + p[ii].w * v3.x;
                acc[ii][1] += p[ii].x * v0.y + p[ii].y * v1.y + p[ii].z * v2.y + p[ii].w * v3.y;
                acc[ii][2] += p[ii].x * v0.z + p[ii].y * v1.z + p[ii].z * v2.z + p[ii].w * v3.z;
                acc[ii][3] += p[ii].x * v0.w + p[ii].y * v1.w + p[ii].z * v2.w + p[ii].w * v3.w;
            }
        }
    }

    // epilogue: divide by l, write out
    #pragma unroll
    for (int ii = 0; ii < 4; ++ii) {
        float inv = 1.f / lrow[ii];
        float4 o = make_float4(acc[ii][0] * inv, acc[ii][1] * inv,
                               acc[ii][2] * inv, acc[ii][3] * inv);
        size_t row = (size_t)b * T_DIM + qRow + ty * 4 + ii;
        *(float4*)&out[row * HS_DIM + tx * 4] = o;
    }
}

extern "C" void kernel_launch(void* const* d_in, const int* in_sizes, int n_in,
                              void* d_out, int out_size) {
    const float* x  = (const float*)d_in[0];
    const float* Wk = (const float*)d_in[1];
    const float* Wv = (const float*)d_in[2];
    float* out = (float*)d_out;

    const int smemProj = 3 * 64 * PITCH * sizeof(float);  // 52224 B
    const int smemAttn = 4 * 64 * PITCH * sizeof(float);  // 69632 B
    cudaFuncSetAttribute(proj_kernel, cudaFuncAttributeMaxDynamicSharedMemorySize, smemProj);
    cudaFuncSetAttribute(attn_kernel, cudaFuncAttributeMaxDynamicSharedMemorySize, smemAttn);

    proj_kernel<<<(B_DIM * T_DIM) / 64, 256, smemProj>>>(x, Wk, Wv);
    attn_kernel<<<dim3(64, B_DIM), 256, smemAttn>>>(out);
}

// round 3
// speedup vs baseline: 3.2041x; 3.2041x over previous
#include <cuda_runtime.h>
#include <cstdint>

#define B_DIM 4
#define T_DIM 4096
#define D_DIM 1024
#define HS 64
#define PB 72  // bf16 pitch (144B): banks (4r+t) distinct for 8x4 frag-load pattern

// Scratch for projected K and QV (q == v in this model).
__device__ float g_k[B_DIM * T_DIM * HS];
__device__ float g_qv[B_DIM * T_DIM * HS];

// pack two floats -> bf16x2 (lo in lower 16 bits)
__device__ __forceinline__ uint32_t bpack(float lo, float hi) {
    uint32_t r;
    asm("cvt.rn.bf16x2.f32 %0, %1, %2;" : "=r"(r) : "f"(hi), "f"(lo));
    return r;
}

__device__ __forceinline__ void mma_bf16(float* c, uint32_t a0, uint32_t a1,
                                         uint32_t a2, uint32_t a3,
                                         uint32_t b0, uint32_t b1) {
    asm volatile(
        "mma.sync.aligned.m16n8k16.row.col.f32.bf16.bf16.f32 "
        "{%0,%1,%2,%3}, {%4,%5,%6,%7}, {%8,%9}, {%0,%1,%2,%3};"
        : "+f"(c[0]), "+f"(c[1]), "+f"(c[2]), "+f"(c[3])
        : "r"(a0), "r"(a1), "r"(a2), "r"(a3), "r"(b0), "r"(b1));
}

// split-store 2 consecutive floats into hi/lo bf16 arrays at even offset
__device__ __forceinline__ void sstore2(uint16_t* Sh, uint16_t* Sl, int off,
                                        float a, float b) {
    uint32_t hp = bpack(a, b);
    float la = a - __uint_as_float(hp << 16);
    float lb = b - __uint_as_float(hp & 0xffff0000u);
    *(uint32_t*)&Sh[off] = hp;
    *(uint32_t*)&Sl[off] = bpack(la, lb);
}

// scalar transpose store (for V^T)
__device__ __forceinline__ void tstore(uint16_t* Th, uint16_t* Tl, int off, float f) {
    uint32_t hp = bpack(f, 0.f);
    float lo = f - __uint_as_float(hp << 16);
    Th[off] = (uint16_t)hp;
    Tl[off] = (uint16_t)bpack(lo, 0.f);
}

#define LD32(arr, idx) (*(const uint32_t*)&(arr)[idx])

// ---------------------------------------------------------------------------
// Projection: k = x@Wk^T, qv = x@Wv^T via bf16 hi/lo 3-MMA compensation.
// CTA: 64 rows, 128 threads (4 warps x 16 rows), K-chunks of 64.
// ---------------------------------------------------------------------------
__global__ __launch_bounds__(128) void proj_kernel(const float* __restrict__ x,
                                                   const float* __restrict__ Wk,
                                                   const float* __restrict__ Wv) {
    extern __shared__ uint16_t sm[];
    uint16_t* sXh = sm;
    uint16_t* sXl = sXh + 64 * PB;
    uint16_t* sKh = sXl + 64 * PB;
    uint16_t* sKl = sKh + 64 * PB;
    uint16_t* sVh = sKl + 64 * PB;
    uint16_t* sVl = sVh + 64 * PB;

    const int tid = threadIdx.x;
    const int w = tid >> 5, lane = tid & 31, g = lane >> 2, t = lane & 3;
    const int RB = blockIdx.x * 64;
    const int m0 = w * 16;

    float accK[8][4] = {};
    float accV[8][4] = {};

    for (int d0 = 0; d0 < D_DIM; d0 += 64) {
        __syncthreads();
        #pragma unroll
        for (int l = 0; l < 8; ++l) {
            int idx = tid + l * 128;  // float4 index 0..1023
            int r = idx >> 4, c = (idx & 15) * 4;
            float4 fx = *(const float4*)&x[(size_t)(RB + r) * D_DIM + d0 + c];
            sstore2(sXh, sXl, r * PB + c, fx.x, fx.y);
            sstore2(sXh, sXl, r * PB + c + 2, fx.z, fx.w);
            float4 fk = *(const float4*)&Wk[(size_t)r * D_DIM + d0 + c];
            sstore2(sKh, sKl, r * PB + c, fk.x, fk.y);
            sstore2(sKh, sKl, r * PB + c + 2, fk.z, fk.w);
            float4 fv = *(const float4*)&Wv[(size_t)r * D_DIM + d0 + c];
            sstore2(sVh, sVl, r * PB + c, fv.x, fv.y);
            sstore2(sVh, sVl, r * PB + c + 2, fv.z, fv.w);
        }
        __syncthreads();

        #pragma unroll
        for (int k0 = 0; k0 < 64; k0 += 16) {
            int ra = (m0 + g) * PB + k0 + 2 * t;
            uint32_t ah0 = LD32(sXh, ra);
            uint32_t ah1 = LD32(sXh, ra + 8 * PB);
            uint32_t ah2 = LD32(sXh, ra + 8);
            uint32_t ah3 = LD32(sXh, ra + 8 * PB + 8);
            uint32_t al0 = LD32(sXl, ra);
            uint32_t al1 = LD32(sXl, ra + 8 * PB);
            uint32_t al2 = LD32(sXl, ra + 8);
            uint32_t al3 = LD32(sXl, ra + 8 * PB + 8);
            #pragma unroll
            for (int j = 0; j < 8; ++j) {
                int rb = (8 * j + g) * PB + k0 + 2 * t;
                uint32_t kh0 = LD32(sKh, rb), kh1 = LD32(sKh, rb + 8);
                uint32_t kl0 = LD32(sKl, rb), kl1 = LD32(sKl, rb + 8);
                mma_bf16(accK[j], ah0, ah1, ah2, ah3, kh0, kh1);
                mma_bf16(accK[j], ah0, ah1, ah2, ah3, kl0, kl1);
                mma_bf16(accK[j], al0, al1, al2, al3, kh0, kh1);
                uint32_t vh0 = LD32(sVh, rb), vh1 = LD32(sVh, rb + 8);
                uint32_t vl0 = LD32(sVl, rb), vl1 = LD32(sVl, rb + 8);
                mma_bf16(accV[j], ah0, ah1, ah2, ah3, vh0, vh1);
                mma_bf16(accV[j], ah0, ah1, ah2, ah3, vl0, vl1);
                mma_bf16(accV[j], al0, al1, al2, al3, vh0, vh1);
            }
        }
    }

    #pragma unroll
    for (int j = 0; j < 8; ++j) {
        size_t row0 = RB + m0 + g;
        int col = 8 * j + 2 * t;
        *(float2*)&g_k[row0 * HS + col] = make_float2(accK[j][0], accK[j][1]);
        *(float2*)&g_k[(row0 + 8) * HS + col] = make_float2(accK[j][2], accK[j][3]);
        *(float2*)&g_qv[row0 * HS + col] = make_float2(accV[j][0], accV[j][1]);
        *(float2*)&g_qv[(row0 + 8) * HS + col] = make_float2(accV[j][2], accV[j][3]);
    }
}

// ---------------------------------------------------------------------------
// Flash attention with bf16 hi/lo MMA. CTA: 64 q-rows, 128 thr (4 warps).
// ---------------------------------------------------------------------------
__global__ __launch_bounds__(128) void attn_kernel(float* __restrict__ out) {
    extern __shared__ uint16_t sm[];
    uint16_t* sQh = sm;
    uint16_t* sQl = sQh + 64 * PB;
    uint16_t* sKh = sQl + 64 * PB;
    uint16_t* sKl = sKh + 64 * PB;
    uint16_t* sVth = sKl + 64 * PB;  // V transposed: [hs][key]
    uint16_t* sVtl = sVth + 64 * PB;

    const int tid = threadIdx.x;
    const int w = tid >> 5, lane = tid & 31, g = lane >> 2, t = lane & 3;
    const int b = blockIdx.y;
    const int mblk = 63 - blockIdx.x;  // longest first
    const int qRow = mblk * 64;
    const int m0 = w * 16;

    const float* Kb = g_k + (size_t)b * T_DIM * HS;
    const float* Vb = g_qv + (size_t)b * T_DIM * HS;

    // Q tile -> smem hi/lo
    #pragma unroll
    for (int l = 0; l < 8; ++l) {
        int idx = tid + l * 128;
        int r = idx >> 4, c = (idx & 15) * 4;
        float4 f = *(const float4*)&Vb[(size_t)(qRow + r) * HS + c];
        sstore2(sQh, sQl, r * PB + c, f.x, f.y);
        sstore2(sQh, sQl, r * PB + c + 2, f.z, f.w);
    }
    __syncthreads();

    // Q A-fragments into registers (4 k-chunks)
    uint32_t qh[4][4], ql[4][4];
    #pragma unroll
    for (int kk = 0; kk < 4; ++kk) {
        int ra = (m0 + g) * PB + kk * 16 + 2 * t;
        qh[kk][0] = LD32(sQh, ra);
        qh[kk][1] = LD32(sQh, ra + 8 * PB);
        qh[kk][2] = LD32(sQh, ra + 8);
        qh[kk][3] = LD32(sQh, ra + 8 * PB + 8);
        ql[kk][0] = LD32(sQl, ra);
        ql[kk][1] = LD32(sQl, ra + 8 * PB);
        ql[kk][2] = LD32(sQl, ra + 8);
        ql[kk][3] = LD32(sQl, ra + 8 * PB + 8);
    }

    float acc[8][4] = {};
    float mrow[2] = {-1e30f, -1e30f};
    float lrow[2] = {0.f, 0.f};
    const float LOG2E = 1.4426950408889634f;

    for (int kb = 0; kb <= mblk; ++kb) {
        __syncthreads();  // previous iteration's reads done
        #pragma unroll
        for (int l = 0; l < 8; ++l) {
            int idx = tid + l * 128;
            int r = idx >> 4, c = (idx & 15) * 4;
            float4 fk = *(const float4*)&Kb[(size_t)(kb * 64 + r) * HS + c];
            sstore2(sKh, sKl, r * PB + c, fk.x, fk.y);
            sstore2(sKh, sKl, r * PB + c + 2, fk.z, fk.w);
            float4 fv = *(const float4*)&Vb[(size_t)(kb * 64 + r) * HS + c];
            tstore(sVth, sVtl, (c + 0) * PB + r, fv.x);
            tstore(sVth, sVtl, (c + 1) * PB + r, fv.y);
            tstore(sVth, sVtl, (c + 2) * PB + r, fv.z);
            tstore(sVth, sVtl, (c + 3) * PB + r, fv.w);
        }
        __syncthreads();

        // S = Q @ K^T (warp: 16x64)
        float s[8][4] = {};
        #pragma unroll
        for (int kk = 0; kk < 4; ++kk) {
            #pragma unroll
            for (int j = 0; j < 8; ++j) {
                int rb = (8 * j + g) * PB + kk * 16 + 2 * t;
                uint32_t bh0 = LD32(sKh, rb), bh1 = LD32(sKh, rb + 8);
                uint32_t bl0 = LD32(sKl, rb), bl1 = LD32(sKl, rb + 8);
                mma_bf16(s[j], qh[kk][0], qh[kk][1], qh[kk][2], qh[kk][3], bh0, bh1);
                mma_bf16(s[j], qh[kk][0], qh[kk][1], qh[kk][2], qh[kk][3], bl0, bl1);
                mma_bf16(s[j], ql[kk][0], ql[kk][1], ql[kk][2], ql[kk][3], bh0, bh1);
            }
        }

        // scale + causal mask (diag block only)
        const bool diag = (kb == mblk);
        const int r0 = m0 + g, r1 = r0 + 8;
        #pragma unroll
        for (int j = 0; j < 8; ++j) {
            int c0 = 8 * j + 2 * t, c1 = c0 + 1;
            s[j][0] = (diag && c0 > r0) ? -1e30f : s[j][0] * 0.125f;
            s[j][1] = (diag && c1 > r0) ? -1e30f : s[j][1] * 0.125f;
            s[j][2] = (diag && c0 > r1) ? -1e30f : s[j][2] * 0.125f;
            s[j][3] = (diag && c1 > r1) ? -1e30f : s[j][3] * 0.125f;
        }

        // online softmax: rows r0 (regs 0,1) and r1 (regs 2,3)
        float mx0 = -1e30f, mx1 = -1e30f;
        #pragma unroll
        for (int j = 0; j < 8; ++j) {
            mx0 = fmaxf(mx0, fmaxf(s[j][0], s[j][1]));
            mx1 = fmaxf(mx1, fmaxf(s[j][2], s[j][3]));
        }
        mx0 = fmaxf(mx0, __shfl_xor_sync(0xffffffffu, mx0, 1));
        mx0 = fmaxf(mx0, __shfl_xor_sync(0xffffffffu, mx0, 2));
        mx1 = fmaxf(mx1, __shfl_xor_sync(0xffffffffu, mx1, 1));
        mx1 = fmaxf(mx1, __shfl_xor_sync(0xffffffffu, mx1, 2));
        float mn0 = fmaxf(mrow[0], mx0), mn1 = fmaxf(mrow[1], mx1);
        float cr0 = exp2f((mrow[0] - mn0) * LOG2E);
        float cr1 = exp2f((mrow[1] - mn1) * LOG2E);
        float sum0 = 0.f, sum1 = 0.f;
        #pragma unroll
        for (int j = 0; j < 8; ++j) {
            s[j][0] = exp2f((s[j][0] - mn0) * LOG2E);
            s[j][1] = exp2f((s[j][1] - mn0) * LOG2E);
            s[j][2] = exp2f((s[j][2] - mn1) * LOG2E);
            s[j][3] = exp2f((s[j][3] - mn1) * LOG2E);
            sum0 += s[j][0] + s[j][1];
            sum1 += s[j][2] + s[j][3];
        }
        sum0 += __shfl_xor_sync(0xffffffffu, sum0, 1);
        sum0 += __shfl_xor_sync(0xffffffffu, sum0, 2);
        sum1 += __shfl_xor_sync(0xffffffffu, sum1, 1);
        sum1 += __shfl_xor_sync(0xffffffffu, sum1, 2);
        lrow[0] = lrow[0] * cr0 + sum0;
        lrow[1] = lrow[1] * cr1 + sum1;
        mrow[0] = mn0;
        mrow[1] = mn1;
        #pragma unroll
        for (int j = 0; j < 8; ++j) {
            acc[j][0] *= cr0;
            acc[j][1] *= cr0;
            acc[j][2] *= cr1;
            acc[j][3] *= cr1;
        }

        // P (C-layout) -> A-fragments, hi/lo, then O += P @ V
        #pragma unroll
        for (int kk = 0; kk < 4; ++kk) {
            uint32_t ph[4], pl[4];
            float* pA = s[2 * kk];
            float* pB = s[2 * kk + 1];
            ph[0] = bpack(pA[0], pA[1]);
            ph[1] = bpack(pA[2], pA[3]);
            ph[2] = bpack(pB[0], pB[1]);
            ph[3] = bpack(pB[2], pB[3]);
            pl[0] = bpack(pA[0] - __uint_as_float(ph[0] << 16),
                          pA[1] - __uint_as_float(ph[0] & 0xffff0000u));
            pl[1] = bpack(pA[2] - __uint_as_float(ph[1] << 16),
                          pA[3] - __uint_as_float(ph[1] & 0xffff0000u));
            pl[2] = bpack(pB[0] - __uint_as_float(ph[2] << 16),
                          pB[1] - __uint_as_float(ph[2] & 0xffff0000u));
            pl[3] = bpack(pB[2] - __uint_as_float(ph[3] << 16),
                          pB[3] - __uint_as_float(ph[3] & 0xffff0000u));
            #pragma unroll
            for (int j = 0; j < 8; ++j) {
                int rb = (8 * j + g) * PB + kk * 16 + 2 * t;
                uint32_t vh0 = LD32(sVth, rb), vh1 = LD32(sVth, rb + 8);
                uint32_t vl0 = LD32(sVtl, rb), vl1 = LD32(sVtl, rb + 8);
                mma_bf16(acc[j], ph[0], ph[1], ph[2], ph[3], vh0, vh1);
                mma_bf16(acc[j], ph[0], ph[1], ph[2], ph[3], vl0, vl1);
                mma_bf16(acc[j], pl[0], pl[1], pl[2], pl[3], vh0, vh1);
            }
        }
    }

    float inv0 = 1.f / lrow[0], inv1 = 1.f / lrow[1];
    #pragma unroll
    for (int j = 0; j < 8; ++j) {
        size_t row0 = (size_t)b * T_DIM + qRow + m0 + g;
        int col = 8 * j + 2 * t;
        *(float2*)&out[row0 * HS + col] = make_float2(acc[j][0] * inv0, acc[j][1] * inv0);
        *(float2*)&out[(row0 + 8) * HS + col] = make_float2(acc[j][2] * inv1, acc[j][3] * inv1);
    }
}

extern "C" void kernel_launch(void* const* d_in, const int* in_sizes, int n_in,
                              void* d_out, int out_size) {
    const float* x = (const float*)d_in[0];
    const float* Wk = (const float*)d_in[1];
    const float* Wv = (const float*)d_in[2];
    float* out = (float*)d_out;

    const int smemBytes = 6 * 64 * PB * sizeof(uint16_t);  // 55296
    cudaFuncSetAttribute(proj_kernel, cudaFuncAttributeMaxDynamicSharedMemorySize, smemBytes);
    cudaFuncSetAttribute(attn_kernel, cudaFuncAttributeMaxDynamicSharedMemorySize, smemBytes);

    proj_kernel<<<(B_DIM * T_DIM) / 64, 128, smemBytes>>>(x, Wk, Wv);
    attn_kernel<<<dim3(64, B_DIM), 128, smemBytes>>>(out);
}

// round 4
// speedup vs baseline: 4.2731x; 1.3336x over previous
#include <cuda_runtime.h>
#include <cstdint>

#define B_DIM 4
#define T_DIM 4096
#define D_DIM 1024
#define HS 64
#define PB 72  // bf16 pitch: 36 banks/row -> conflict-free 8x4 frag loads

// Projected tensors stored as bf16 hi/lo pairs (fp32 = hi + lo to ~16 mantissa bits)
__device__ __align__(16) uint16_t g_kh[B_DIM * T_DIM * HS];
__device__ __align__(16) uint16_t g_kl[B_DIM * T_DIM * HS];
__device__ __align__(16) uint16_t g_qh[B_DIM * T_DIM * HS];
__device__ __align__(16) uint16_t g_ql[B_DIM * T_DIM * HS];
__device__ __align__(16) uint16_t g_vth[B_DIM * HS * T_DIM];  // QV transposed [b][h][t]
__device__ __align__(16) uint16_t g_vtl[B_DIM * HS * T_DIM];

__device__ __forceinline__ uint32_t bpack(float lo, float hi) {
    uint32_t r;
    asm("cvt.rn.bf16x2.f32 %0, %1, %2;" : "=r"(r) : "f"(hi), "f"(lo));
    return r;
}

__device__ __forceinline__ void packpair(float a, float b, uint32_t& h, uint32_t& l) {
    h = bpack(a, b);
    l = bpack(a - __uint_as_float(h << 16), b - __uint_as_float(h & 0xffff0000u));
}

__device__ __forceinline__ void mma_bf16(float* c, uint32_t a0, uint32_t a1,
                                         uint32_t a2, uint32_t a3,
                                         uint32_t b0, uint32_t b1) {
    asm volatile(
        "mma.sync.aligned.m16n8k16.row.col.f32.bf16.bf16.f32 "
        "{%0,%1,%2,%3}, {%4,%5,%6,%7}, {%8,%9}, {%0,%1,%2,%3};"
        : "+f"(c[0]), "+f"(c[1]), "+f"(c[2]), "+f"(c[3])
        : "r"(a0), "r"(a1), "r"(a2), "r"(a3), "r"(b0), "r"(b1));
}

// split-store 2 consecutive floats into hi/lo bf16 smem arrays
__device__ __forceinline__ void sstore2(uint16_t* Sh, uint16_t* Sl, int off,
                                        float a, float b) {
    uint32_t h, l;
    packpair(a, b, h, l);
    *(uint32_t*)&Sh[off] = h;
    *(uint32_t*)&Sl[off] = l;
}

__device__ __forceinline__ void cpa16(uint32_t dst, const void* src) {
    asm volatile("cp.async.cg.shared.global [%0], [%1], 16;" :: "r"(dst), "l"(src));
}

#define LD32(arr, idx) (*(const uint32_t*)&(arr)[idx])

// ---------------------------------------------------------------------------
// Projection: k = x@Wk^T, qv = x@Wv^T via bf16 hi/lo 3-MMA compensation.
// Writes all outputs as bf16 hi/lo (k, qv row-major; qv also transposed).
// ---------------------------------------------------------------------------
__global__ __launch_bounds__(128) void proj_kernel(const float* __restrict__ x,
                                                   const float* __restrict__ Wk,
                                                   const float* __restrict__ Wv) {
    extern __shared__ __align__(16) uint16_t sm[];
    uint16_t* sXh = sm;
    uint16_t* sXl = sXh + 64 * PB;
    uint16_t* sKh = sXl + 64 * PB;
    uint16_t* sKl = sKh + 64 * PB;
    uint16_t* sVh = sKl + 64 * PB;
    uint16_t* sVl = sVh + 64 * PB;

    const int tid = threadIdx.x;
    const int w = tid >> 5, lane = tid & 31, g = lane >> 2, t = lane & 3;
    const int RB = blockIdx.x * 64;
    const int m0 = w * 16;

    float accK[8][4] = {};
    float accV[8][4] = {};

    for (int d0 = 0; d0 < D_DIM; d0 += 64) {
        __syncthreads();
        #pragma unroll
        for (int l = 0; l < 8; ++l) {
            int idx = tid + l * 128;
            int r = idx >> 4, c = (idx & 15) * 4;
            float4 fx = *(const float4*)&x[(size_t)(RB + r) * D_DIM + d0 + c];
            sstore2(sXh, sXl, r * PB + c, fx.x, fx.y);
            sstore2(sXh, sXl, r * PB + c + 2, fx.z, fx.w);
            float4 fk = *(const float4*)&Wk[(size_t)r * D_DIM + d0 + c];
            sstore2(sKh, sKl, r * PB + c, fk.x, fk.y);
            sstore2(sKh, sKl, r * PB + c + 2, fk.z, fk.w);
            float4 fv = *(const float4*)&Wv[(size_t)r * D_DIM + d0 + c];
            sstore2(sVh, sVl, r * PB + c, fv.x, fv.y);
            sstore2(sVh, sVl, r * PB + c + 2, fv.z, fv.w);
        }
        __syncthreads();

        #pragma unroll
        for (int k0 = 0; k0 < 64; k0 += 16) {
            int ra = (m0 + g) * PB + k0 + 2 * t;
            uint32_t ah0 = LD32(sXh, ra);
            uint32_t ah1 = LD32(sXh, ra + 8 * PB);
            uint32_t ah2 = LD32(sXh, ra + 8);
            uint32_t ah3 = LD32(sXh, ra + 8 * PB + 8);
            uint32_t al0 = LD32(sXl, ra);
            uint32_t al1 = LD32(sXl, ra + 8 * PB);
            uint32_t al2 = LD32(sXl, ra + 8);
            uint32_t al3 = LD32(sXl, ra + 8 * PB + 8);
            #pragma unroll
            for (int j = 0; j < 8; ++j) {
                int rb = (8 * j + g) * PB + k0 + 2 * t;
                uint32_t kh0 = LD32(sKh, rb), kh1 = LD32(sKh, rb + 8);
                uint32_t kl0 = LD32(sKl, rb), kl1 = LD32(sKl, rb + 8);
                mma_bf16(accK[j], ah0, ah1, ah2, ah3, kh0, kh1);
                mma_bf16(accK[j], ah0, ah1, ah2, ah3, kl0, kl1);
                mma_bf16(accK[j], al0, al1, al2, al3, kh0, kh1);
                uint32_t vh0 = LD32(sVh, rb), vh1 = LD32(sVh, rb + 8);
                uint32_t vl0 = LD32(sVl, rb), vl1 = LD32(sVl, rb + 8);
                mma_bf16(accV[j], ah0, ah1, ah2, ah3, vh0, vh1);
                mma_bf16(accV[j], ah0, ah1, ah2, ah3, vl0, vl1);
                mma_bf16(accV[j], al0, al1, al2, al3, vh0, vh1);
            }
        }
    }

    const int row0 = RB + m0 + g;
    const int batch = row0 / T_DIM;
    const int tl0 = row0 % T_DIM;

    #pragma unroll
    for (int j = 0; j < 8; ++j) {
        int col = 8 * j + 2 * t;
        uint32_t h, l;
        // K rows row0, row0+8
        packpair(accK[j][0], accK[j][1], h, l);
        *(uint32_t*)&g_kh[(size_t)row0 * HS + col] = h;
        *(uint32_t*)&g_kl[(size_t)row0 * HS + col] = l;
        packpair(accK[j][2], accK[j][3], h, l);
        *(uint32_t*)&g_kh[(size_t)(row0 + 8) * HS + col] = h;
        *(uint32_t*)&g_kl[(size_t)(row0 + 8) * HS + col] = l;
        // QV rows
        packpair(accV[j][0], accV[j][1], h, l);
        *(uint32_t*)&g_qh[(size_t)row0 * HS + col] = h;
        *(uint32_t*)&g_ql[(size_t)row0 * HS + col] = l;
        packpair(accV[j][2], accV[j][3], h, l);
        *(uint32_t*)&g_qh[(size_t)(row0 + 8) * HS + col] = h;
        *(uint32_t*)&g_ql[(size_t)(row0 + 8) * HS + col] = l;
        // QV transposed [b][h][t], scalar scattered stores
        #pragma unroll
        for (int q = 0; q < 4; ++q) {
            float v = accV[j][q];
            int cc = col + (q & 1);
            int tt = tl0 + (q >> 1) * 8;
            uint32_t hp = bpack(v, 0.f);
            float lo = v - __uint_as_float(hp << 16);
            size_t off = ((size_t)batch * HS + cc) * T_DIM + tt;
            g_vth[off] = (uint16_t)hp;
            g_vtl[off] = (uint16_t)bpack(lo, 0.f);
        }
    }
}

// ---------------------------------------------------------------------------
// Flash attention, cp.async double-buffered, no per-iteration conversion.
// ---------------------------------------------------------------------------
#define ABYTES (64 * PB * 2)          // 9216 bytes per array
#define BUFBYTES (4 * ABYTES)         // Kh,Kl,Vth,Vtl
#define AU16 (64 * PB)

__global__ __launch_bounds__(128) void attn_kernel(float* __restrict__ out) {
    extern __shared__ __align__(16) uint16_t sm[];
    const uint32_t smb = (uint32_t)__cvta_generic_to_shared(sm);

    const int tid = threadIdx.x;
    const int w = tid >> 5, lane = tid & 31, g = lane >> 2, t = lane & 3;
    const int b = blockIdx.y;
    const int mblk = 63 - blockIdx.x;  // longest first
    const int qRow = mblk * 64;
    const int m0 = w * 16;

    // per-thread cp.async source/dest precompute
    const int lr = tid >> 3;           // 0..15 (row group start)
    const int lc = (tid & 7) * 8;      // 16B chunk col

    // Q A-fragments straight from global
    uint32_t qh[4][4], ql[4][4];
    {
        const uint16_t* Qh = g_qh + (size_t)b * T_DIM * HS;
        const uint16_t* Ql = g_ql + (size_t)b * T_DIM * HS;
        int base = (qRow + m0 + g) * HS + 2 * t;
        #pragma unroll
        for (int kk = 0; kk < 4; ++kk) {
            int o = base + kk * 16;
            qh[kk][0] = LD32(Qh, o);
            qh[kk][1] = LD32(Qh, o + 8 * HS);
            qh[kk][2] = LD32(Qh, o + 8);
            qh[kk][3] = LD32(Qh, o + 8 * HS + 8);
            ql[kk][0] = LD32(Ql, o);
            ql[kk][1] = LD32(Ql, o + 8 * HS);
            ql[kk][2] = LD32(Ql, o + 8);
            ql[kk][3] = LD32(Ql, o + 8 * HS + 8);
        }
    }

    // issue loads for key-block kb into buffer buf
    auto issue_tile = [&](int buf, int kb) {
        uint32_t base = smb + buf * BUFBYTES;
        #pragma unroll
        for (int l = 0; l < 4; ++l) {
            int r = lr + l * 16;
            uint32_t soff = (uint32_t)(r * PB + lc) * 2;
            size_t gk = ((size_t)b * T_DIM + kb * 64 + r) * HS + lc;
            cpa16(base + soff, &g_kh[gk]);
            cpa16(base + ABYTES + soff, &g_kl[gk]);
            size_t gv = ((size_t)b * HS + r) * T_DIM + kb * 64 + lc;
            cpa16(base + 2 * ABYTES + soff, &g_vth[gv]);
            cpa16(base + 3 * ABYTES + soff, &g_vtl[gv]);
        }
        asm volatile("cp.async.commit_group;");
    };

    issue_tile(0, 0);

    float acc[8][4] = {};
    float mrow[2] = {-1e30f, -1e30f};
    float lrow[2] = {0.f, 0.f};
    const float LOG2E = 1.4426950408889634f;

    for (int kb = 0; kb <= mblk; ++kb) {
        asm volatile("cp.async.wait_group 0;" ::: "memory");
        __syncthreads();
        if (kb < mblk) issue_tile((kb + 1) & 1, kb + 1);

        const uint16_t* bKh = sm + (kb & 1) * 4 * AU16;
        const uint16_t* bKl = bKh + AU16;
        const uint16_t* bVh = bKh + 2 * AU16;
        const uint16_t* bVl = bKh + 3 * AU16;

        // S = Q @ K^T
        float s[8][4] = {};
        #pragma unroll
        for (int kk = 0; kk < 4; ++kk) {
            #pragma unroll
            for (int j = 0; j < 8; ++j) {
                int rb = (8 * j + g) * PB + kk * 16 + 2 * t;
                uint32_t bh0 = LD32(bKh, rb), bh1 = LD32(bKh, rb + 8);
                uint32_t bl0 = LD32(bKl, rb), bl1 = LD32(bKl, rb + 8);
                mma_bf16(s[j], qh[kk][0], qh[kk][1], qh[kk][2], qh[kk][3], bh0, bh1);
                mma_bf16(s[j], qh[kk][0], qh[kk][1], qh[kk][2], qh[kk][3], bl0, bl1);
                mma_bf16(s[j], ql[kk][0], ql[kk][1], ql[kk][2], ql[kk][3], bh0, bh1);
            }
        }

        // scale + causal mask (diag block only)
        const bool diag = (kb == mblk);
        const int r0 = m0 + g, r1 = r0 + 8;
        #pragma unroll
        for (int j = 0; j < 8; ++j) {
            int c0 = 8 * j + 2 * t, c1 = c0 + 1;
            s[j][0] = (diag && c0 > r0) ? -1e30f : s[j][0] * 0.125f;
            s[j][1] = (diag && c1 > r0) ? -1e30f : s[j][1] * 0.125f;
            s[j][2] = (diag && c0 > r1) ? -1e30f : s[j][2] * 0.125f;
            s[j][3] = (diag && c1 > r1) ? -1e30f : s[j][3] * 0.125f;
        }

        // online softmax (rows r0: regs 0,1; r1: regs 2,3), width-4 shfl
        float mx0 = -1e30f, mx1 = -1e30f;
        #pragma unroll
        for (int j = 0; j < 8; ++j) {
            mx0 = fmaxf(mx0, fmaxf(s[j][0], s[j][1]));
            mx1 = fmaxf(mx1, fmaxf(s[j][2], s[j][3]));
        }
        mx0 = fmaxf(mx0, __shfl_xor_sync(0xffffffffu, mx0, 1));
        mx0 = fmaxf(mx0, __shfl_xor_sync(0xffffffffu, mx0, 2));
        mx1 = fmaxf(mx1, __shfl_xor_sync(0xffffffffu, mx1, 1));
        mx1 = fmaxf(mx1, __shfl_xor_sync(0xffffffffu, mx1, 2));
        float mn0 = fmaxf(mrow[0], mx0), mn1 = fmaxf(mrow[1], mx1);
        float cr0 = exp2f((mrow[0] - mn0) * LOG2E);
        float cr1 = exp2f((mrow[1] - mn1) * LOG2E);
        float sum0 = 0.f, sum1 = 0.f;
        #pragma unroll
        for (int j = 0; j < 8; ++j) {
            s[j][0] = exp2f((s[j][0] - mn0) * LOG2E);
            s[j][1] = exp2f((s[j][1] - mn0) * LOG2E);
            s[j][2] = exp2f((s[j][2] - mn1) * LOG2E);
            s[j][3] = exp2f((s[j][3] - mn1) * LOG2E);
            sum0 += s[j][0] + s[j][1];
            sum1 += s[j][2] + s[j][3];
        }
        sum0 += __shfl_xor_sync(0xffffffffu, sum0, 1);
        sum0 += __shfl_xor_sync(0xffffffffu, sum0, 2);
        sum1 += __shfl_xor_sync(0xffffffffu, sum1, 1);
        sum1 += __shfl_xor_sync(0xffffffffu, sum1, 2);
        lrow[0] = lrow[0] * cr0 + sum0;
        lrow[1] = lrow[1] * cr1 + sum1;
        mrow[0] = mn0;
        mrow[1] = mn1;
        #pragma unroll
        for (int j = 0; j < 8; ++j) {
            acc[j][0] *= cr0;
            acc[j][1] *= cr0;
            acc[j][2] *= cr1;
            acc[j][3] *= cr1;
        }

        // P -> A-fragments (hi/lo), O += P @ V
        #pragma unroll
        for (int kk = 0; kk < 4; ++kk) {
            uint32_t ph[4], pl[4];
            float* pA = s[2 * kk];
            float* pB = s[2 * kk + 1];
            packpair(pA[0], pA[1], ph[0], pl[0]);
            packpair(pA[2], pA[3], ph[1], pl[1]);
            packpair(pB[0], pB[1], ph[2], pl[2]);
            packpair(pB[2], pB[3], ph[3], pl[3]);
            #pragma unroll
            for (int j = 0; j < 8; ++j) {
                int rb = (8 * j + g) * PB + kk * 16 + 2 * t;
                uint32_t vh0 = LD32(bVh, rb), vh1 = LD32(bVh, rb + 8);
                uint32_t vl0 = LD32(bVl, rb), vl1 = LD32(bVl, rb + 8);
                mma_bf16(acc[j], ph[0], ph[1], ph[2], ph[3], vh0, vh1);
                mma_bf16(acc[j], ph[0], ph[1], ph[2], ph[3], vl0, vl1);
                mma_bf16(acc[j], pl[0], pl[1], pl[2], pl[3], vh0, vh1);
            }
        }
    }

    float inv0 = 1.f / lrow[0], inv1 = 1.f / lrow[1];
    #pragma unroll
    for (int j = 0; j < 8; ++j) {
        size_t row0 = (size_t)b * T_DIM + qRow + m0 + g;
        int col = 8 * j + 2 * t;
        *(float2*)&out[row0 * HS + col] = make_float2(acc[j][0] * inv0, acc[j][1] * inv0);
        *(float2*)&out[(row0 + 8) * HS + col] = make_float2(acc[j][2] * inv1, acc[j][3] * inv1);
    }
}

extern "C" void kernel_launch(void* const* d_in, const int* in_sizes, int n_in,
                              void* d_out, int out_size) {
    const float* x = (const float*)d_in[0];
    const float* Wk = (const float*)d_in[1];
    const float* Wv = (const float*)d_in[2];
    float* out = (float*)d_out;

    const int smemProj = 6 * 64 * PB * sizeof(uint16_t);  // 55296
    const int smemAttn = 2 * BUFBYTES;                    // 73728
    cudaFuncSetAttribute(proj_kernel, cudaFuncAttributeMaxDynamicSharedMemorySize, smemProj);
    cudaFuncSetAttribute(attn_kernel, cudaFuncAttributeMaxDynamicSharedMemorySize, smemAttn);

    proj_kernel<<<(B_DIM * T_DIM) / 64, 128, smemProj>>>(x, Wk, Wv);
    attn_kernel<<<dim3(64, B_DIM), 128, smemAttn>>>(out);
}

// round 5
// speedup vs baseline: 5.4907x; 1.2849x over previous
#include <cuda_runtime.h>
#include <cstdint>

#define B_DIM 4
#define T_DIM 4096
#define D_DIM 1024
#define HS 64
#define PB 72      // bf16 pitch: conflict-free frag loads, 16B-aligned rows
#define NCHUNK 4   // max kv chunks per 64-row q-block
#define CBLK 16    // kv blocks (of 64 keys) per chunk

// Projected tensors as bf16 hi/lo pairs
__device__ __align__(16) uint16_t g_kh[B_DIM * T_DIM * HS];
__device__ __align__(16) uint16_t g_kl[B_DIM * T_DIM * HS];
__device__ __align__(16) uint16_t g_qh[B_DIM * T_DIM * HS];
__device__ __align__(16) uint16_t g_ql[B_DIM * T_DIM * HS];
__device__ __align__(16) uint16_t g_vth[B_DIM * HS * T_DIM];  // QV^T [b][h][t]
__device__ __align__(16) uint16_t g_vtl[B_DIM * HS * T_DIM];

// Preconverted weights: [mat(0=K,1=V)][out 64][d 1024]
__device__ __align__(16) uint16_t g_wh[2 * HS * D_DIM];
__device__ __align__(16) uint16_t g_wl[2 * HS * D_DIM];

// Split-KV partials: unit = ((b*64 + mb)*NCHUNK + chunk)
__device__ float g_po[B_DIM * 64 * NCHUNK * 64 * HS];  // unnormalized O
__device__ float g_pm[B_DIM * 64 * NCHUNK * 64];       // row max (raw scores)
__device__ float g_pl[B_DIM * 64 * NCHUNK * 64];       // row sum

#define CSC 0.1803368801111204f  // 0.125 * log2(e)

__device__ __forceinline__ uint32_t bpack(float lo, float hi) {
    uint32_t r;
    asm("cvt.rn.bf16x2.f32 %0, %1, %2;" : "=r"(r) : "f"(hi), "f"(lo));
    return r;
}
__device__ __forceinline__ void packpair(float a, float b, uint32_t& h, uint32_t& l) {
    h = bpack(a, b);
    l = bpack(a - __uint_as_float(h << 16), b - __uint_as_float(h & 0xffff0000u));
}
__device__ __forceinline__ void mma_bf16(float* c, uint32_t a0, uint32_t a1,
                                         uint32_t a2, uint32_t a3,
                                         uint32_t b0, uint32_t b1) {
    asm volatile(
        "mma.sync.aligned.m16n8k16.row.col.f32.bf16.bf16.f32 "
        "{%0,%1,%2,%3}, {%4,%5,%6,%7}, {%8,%9}, {%0,%1,%2,%3};"
        : "+f"(c[0]), "+f"(c[1]), "+f"(c[2]), "+f"(c[3])
        : "r"(a0), "r"(a1), "r"(a2), "r"(a3), "r"(b0), "r"(b1));
}
__device__ __forceinline__ void sstore2(uint16_t* Sh, uint16_t* Sl, int off,
                                        float a, float b) {
    uint32_t h, l;
    packpair(a, b, h, l);
    *(uint32_t*)&Sh[off] = h;
    *(uint32_t*)&Sl[off] = l;
}
__device__ __forceinline__ void cpa16(uint32_t dst, const void* src) {
    asm volatile("cp.async.cg.shared.global [%0], [%1], 16;" :: "r"(dst), "l"(src));
}
#define LD32(arr, idx) (*(const uint32_t*)&(arr)[idx])

// ---------------------------------------------------------------------------
// One-time weight conversion fp32 -> bf16 hi/lo
// ---------------------------------------------------------------------------
__global__ __launch_bounds__(256) void wconv_kernel(const float* __restrict__ Wk,
                                                    const float* __restrict__ Wv) {
    int i = blockIdx.x * 512 + threadIdx.x * 2;
    uint32_t h, l;
    packpair(Wk[i], Wk[i + 1], h, l);
    *(uint32_t*)&g_wh[i] = h;
    *(uint32_t*)&g_wl[i] = l;
    packpair(Wv[i], Wv[i + 1], h, l);
    *(uint32_t*)&g_wh[HS * D_DIM + i] = h;
    *(uint32_t*)&g_wl[HS * D_DIM + i] = l;
}

// ---------------------------------------------------------------------------
// Projection: k = x@Wk^T, qv = x@Wv^T (bf16 hi/lo 3-MMA). W via cp.async.
// ---------------------------------------------------------------------------
__global__ __launch_bounds__(128) void proj_kernel(const float* __restrict__ x) {
    extern __shared__ __align__(16) uint16_t sm[];
    uint16_t* sXh = sm;
    uint16_t* sXl = sXh + 64 * PB;
    uint16_t* sKh = sXl + 64 * PB;
    uint16_t* sKl = sKh + 64 * PB;
    uint16_t* sVh = sKl + 64 * PB;
    uint16_t* sVl = sVh + 64 * PB;
    const uint32_t smb = (uint32_t)__cvta_generic_to_shared(sm);
    const uint32_t AB = 64 * PB * 2;  // bytes per array

    const int tid = threadIdx.x;
    const int w = tid >> 5, lane = tid & 31, g = lane >> 2, t = lane & 3;
    const int RB = blockIdx.x * 64;
    const int m0 = w * 16;

    float accK[8][4] = {};
    float accV[8][4] = {};

    for (int d0 = 0; d0 < D_DIM; d0 += 64) {
        __syncthreads();
        // W tiles via cp.async (4 arrays x 512 16B-chunks)
        #pragma unroll
        for (int l = 0; l < 4; ++l) {
            int id = tid + l * 128;          // 0..511
            int r = id >> 3, c8 = (id & 7) * 8;
            uint32_t soff = (uint32_t)(r * PB + c8) * 2;
            size_t go = (size_t)r * D_DIM + d0 + c8;
            cpa16(smb + 2 * AB + soff, &g_wh[go]);                 // Wk hi
            cpa16(smb + 3 * AB + soff, &g_wl[go]);                 // Wk lo
            cpa16(smb + 4 * AB + soff, &g_wh[HS * D_DIM + go]);    // Wv hi
            cpa16(smb + 5 * AB + soff, &g_wl[HS * D_DIM + go]);    // Wv lo
        }
        asm volatile("cp.async.commit_group;");
        // x tile: convert fp32 -> hi/lo
        #pragma unroll
        for (int l = 0; l < 8; ++l) {
            int idx = tid + l * 128;
            int r = idx >> 4, c = (idx & 15) * 4;
            float4 fx = *(const float4*)&x[(size_t)(RB + r) * D_DIM + d0 + c];
            sstore2(sXh, sXl, r * PB + c, fx.x, fx.y);
            sstore2(sXh, sXl, r * PB + c + 2, fx.z, fx.w);
        }
        asm volatile("cp.async.wait_group 0;" ::: "memory");
        __syncthreads();

        #pragma unroll
        for (int k0 = 0; k0 < 64; k0 += 16) {
            int ra = (m0 + g) * PB + k0 + 2 * t;
            uint32_t ah0 = LD32(sXh, ra);
            uint32_t ah1 = LD32(sXh, ra + 8 * PB);
            uint32_t ah2 = LD32(sXh, ra + 8);
            uint32_t ah3 = LD32(sXh, ra + 8 * PB + 8);
            uint32_t al0 = LD32(sXl, ra);
            uint32_t al1 = LD32(sXl, ra + 8 * PB);
            uint32_t al2 = LD32(sXl, ra + 8);
            uint32_t al3 = LD32(sXl, ra + 8 * PB + 8);
            #pragma unroll
            for (int j = 0; j < 8; ++j) {
                int rb = (8 * j + g) * PB + k0 + 2 * t;
                uint32_t kh0 = LD32(sKh, rb), kh1 = LD32(sKh, rb + 8);
                uint32_t kl0 = LD32(sKl, rb), kl1 = LD32(sKl, rb + 8);
                mma_bf16(accK[j], ah0, ah1, ah2, ah3, kh0, kh1);
                mma_bf16(accK[j], ah0, ah1, ah2, ah3, kl0, kl1);
                mma_bf16(accK[j], al0, al1, al2, al3, kh0, kh1);
                uint32_t vh0 = LD32(sVh, rb), vh1 = LD32(sVh, rb + 8);
                uint32_t vl0 = LD32(sVl, rb), vl1 = LD32(sVl, rb + 8);
                mma_bf16(accV[j], ah0, ah1, ah2, ah3, vh0, vh1);
                mma_bf16(accV[j], ah0, ah1, ah2, ah3, vl0, vl1);
                mma_bf16(accV[j], al0, al1, al2, al3, vh0, vh1);
            }
        }
    }

    const int row0 = RB + m0 + g;
    const int batch = row0 / T_DIM;
    const int tl0 = row0 % T_DIM;

    #pragma unroll
    for (int j = 0; j < 8; ++j) {
        int col = 8 * j + 2 * t;
        uint32_t h, l;
        packpair(accK[j][0], accK[j][1], h, l);
        *(uint32_t*)&g_kh[(size_t)row0 * HS + col] = h;
        *(uint32_t*)&g_kl[(size_t)row0 * HS + col] = l;
        packpair(accK[j][2], accK[j][3], h, l);
        *(uint32_t*)&g_kh[(size_t)(row0 + 8) * HS + col] = h;
        *(uint32_t*)&g_kl[(size_t)(row0 + 8) * HS + col] = l;
        packpair(accV[j][0], accV[j][1], h, l);
        *(uint32_t*)&g_qh[(size_t)row0 * HS + col] = h;
        *(uint32_t*)&g_ql[(size_t)row0 * HS + col] = l;
        packpair(accV[j][2], accV[j][3], h, l);
        *(uint32_t*)&g_qh[(size_t)(row0 + 8) * HS + col] = h;
        *(uint32_t*)&g_ql[(size_t)(row0 + 8) * HS + col] = l;
        #pragma unroll
        for (int q = 0; q < 4; ++q) {
            float v = accV[j][q];
            int cc = col + (q & 1);
            int tt = tl0 + (q >> 1) * 8;
            uint32_t hp = bpack(v, 0.f);
            float lo = v - __uint_as_float(hp << 16);
            size_t off = ((size_t)batch * HS + cc) * T_DIM + tt;
            g_vth[off] = (uint16_t)hp;
            g_vtl[off] = (uint16_t)bpack(lo, 0.f);
        }
    }
}

// ---------------------------------------------------------------------------
// Split-KV flash attention. Grid (64 qblocks, NCHUNK, B). Writes partials.
// ---------------------------------------------------------------------------
#define ABYTES (64 * PB * 2)
#define BUFBYTES (4 * ABYTES)
#define AU16 (64 * PB)

__global__ __launch_bounds__(128) void attn_kernel() {
    const int mblk = 63 - blockIdx.x;          // longest-first
    const int kb0 = blockIdx.y * CBLK;
    if (kb0 > mblk) return;                    // empty unit
    const int kb1 = min(kb0 + CBLK - 1, mblk);
    const int b = blockIdx.z;
    const int unit = ((b * 64 + mblk) * NCHUNK) + blockIdx.y;

    extern __shared__ __align__(16) uint16_t sm[];
    const uint32_t smb = (uint32_t)__cvta_generic_to_shared(sm);

    const int tid = threadIdx.x;
    const int w = tid >> 5, lane = tid & 31, g = lane >> 2, t = lane & 3;
    const int qRow = mblk * 64;
    const int m0 = w * 16;
    const int lr = tid >> 3;
    const int lc = (tid & 7) * 8;

    // Q A-fragments from global
    uint32_t qh[4][4], ql[4][4];
    {
        const uint16_t* Qh = g_qh + (size_t)b * T_DIM * HS;
        const uint16_t* Ql = g_ql + (size_t)b * T_DIM * HS;
        int base = (qRow + m0 + g) * HS + 2 * t;
        #pragma unroll
        for (int kk = 0; kk < 4; ++kk) {
            int o = base + kk * 16;
            qh[kk][0] = LD32(Qh, o);
            qh[kk][1] = LD32(Qh, o + 8 * HS);
            qh[kk][2] = LD32(Qh, o + 8);
            qh[kk][3] = LD32(Qh, o + 8 * HS + 8);
            ql[kk][0] = LD32(Ql, o);
            ql[kk][1] = LD32(Ql, o + 8 * HS);
            ql[kk][2] = LD32(Ql, o + 8);
            ql[kk][3] = LD32(Ql, o + 8 * HS + 8);
        }
    }

    auto issue_tile = [&](int buf, int kb) {
        uint32_t base = smb + buf * BUFBYTES;
        #pragma unroll
        for (int l = 0; l < 4; ++l) {
            int r = lr + l * 16;
            uint32_t soff = (uint32_t)(r * PB + lc) * 2;
            size_t gk = ((size_t)b * T_DIM + kb * 64 + r) * HS + lc;
            cpa16(base + soff, &g_kh[gk]);
            cpa16(base + ABYTES + soff, &g_kl[gk]);
            size_t gv = ((size_t)b * HS + r) * T_DIM + kb * 64 + lc;
            cpa16(base + 2 * ABYTES + soff, &g_vth[gv]);
            cpa16(base + 3 * ABYTES + soff, &g_vtl[gv]);
        }
        asm volatile("cp.async.commit_group;");
    };

    issue_tile(kb0 & 1, kb0);

    float acc[8][4] = {};
    float mrow[2] = {-1e30f, -1e30f};
    float lrow[2] = {0.f, 0.f};

    for (int kb = kb0; kb <= kb1; ++kb) {
        asm volatile("cp.async.wait_group 0;" ::: "memory");
        __syncthreads();
        if (kb < kb1) issue_tile((kb + 1) & 1, kb + 1);

        const uint16_t* bKh = sm + (kb & 1) * 4 * AU16;
        const uint16_t* bKl = bKh + AU16;
        const uint16_t* bVh = bKh + 2 * AU16;
        const uint16_t* bVl = bKh + 3 * AU16;

        float s[8][4] = {};
        #pragma unroll
        for (int kk = 0; kk < 4; ++kk) {
            #pragma unroll
            for (int j = 0; j < 8; ++j) {
                int rb = (8 * j + g) * PB + kk * 16 + 2 * t;
                uint32_t bh0 = LD32(bKh, rb), bh1 = LD32(bKh, rb + 8);
                uint32_t bl0 = LD32(bKl, rb), bl1 = LD32(bKl, rb + 8);
                mma_bf16(s[j], qh[kk][0], qh[kk][1], qh[kk][2], qh[kk][3], bh0, bh1);
                mma_bf16(s[j], qh[kk][0], qh[kk][1], qh[kk][2], qh[kk][3], bl0, bl1);
                mma_bf16(s[j], ql[kk][0], ql[kk][1], ql[kk][2], ql[kk][3], bh0, bh1);
            }
        }

        // causal mask (diag block only); scores kept raw (scale folded into exp)
        if (kb == mblk) {
            const int r0 = m0 + g, r1 = r0 + 8;
            #pragma unroll
            for (int j = 0; j < 8; ++j) {
                int c0 = 8 * j + 2 * t, c1 = c0 + 1;
                if (c0 > r0) s[j][0] = -1e30f;
                if (c1 > r0) s[j][1] = -1e30f;
                if (c0 > r1) s[j][2] = -1e30f;
                if (c1 > r1) s[j][3] = -1e30f;
            }
        }

        float mx0 = -1e30f, mx1 = -1e30f;
        #pragma unroll
        for (int j = 0; j < 8; ++j) {
            mx0 = fmaxf(mx0, fmaxf(s[j][0], s[j][1]));
            mx1 = fmaxf(mx1, fmaxf(s[j][2], s[j][3]));
        }
        mx0 = fmaxf(mx0, __shfl_xor_sync(0xffffffffu, mx0, 1));
        mx0 = fmaxf(mx0, __shfl_xor_sync(0xffffffffu, mx0, 2));
        mx1 = fmaxf(mx1, __shfl_xor_sync(0xffffffffu, mx1, 1));
        mx1 = fmaxf(mx1, __shfl_xor_sync(0xffffffffu, mx1, 2));
        float mn0 = fmaxf(mrow[0], mx0), mn1 = fmaxf(mrow[1], mx1);
        float cr0 = exp2f((mrow[0] - mn0) * CSC);
        float cr1 = exp2f((mrow[1] - mn1) * CSC);
        float sum0 = 0.f, sum1 = 0.f;
        #pragma unroll
        for (int j = 0; j < 8; ++j) {
            s[j][0] = exp2f((s[j][0] - mn0) * CSC);
            s[j][1] = exp2f((s[j][1] - mn0) * CSC);
            s[j][2] = exp2f((s[j][2] - mn1) * CSC);
            s[j][3] = exp2f((s[j][3] - mn1) * CSC);
            sum0 += s[j][0] + s[j][1];
            sum1 += s[j][2] + s[j][3];
        }
        sum0 += __shfl_xor_sync(0xffffffffu, sum0, 1);
        sum0 += __shfl_xor_sync(0xffffffffu, sum0, 2);
        sum1 += __shfl_xor_sync(0xffffffffu, sum1, 1);
        sum1 += __shfl_xor_sync(0xffffffffu, sum1, 2);
        lrow[0] = lrow[0] * cr0 + sum0;
        lrow[1] = lrow[1] * cr1 + sum1;
        mrow[0] = mn0;
        mrow[1] = mn1;
        #pragma unroll
        for (int j = 0; j < 8; ++j) {
            acc[j][0] *= cr0;
            acc[j][1] *= cr0;
            acc[j][2] *= cr1;
            acc[j][3] *= cr1;
        }

        #pragma unroll
        for (int kk = 0; kk < 4; ++kk) {
            uint32_t ph[4], pl[4];
            float* pA = s[2 * kk];
            float* pB = s[2 * kk + 1];
            packpair(pA[0], pA[1], ph[0], pl[0]);
            packpair(pA[2], pA[3], ph[1], pl[1]);
            packpair(pB[0], pB[1], ph[2], pl[2]);
            packpair(pB[2], pB[3], ph[3], pl[3]);
            #pragma unroll
            for (int j = 0; j < 8; ++j) {
                int rb = (8 * j + g) * PB + kk * 16 + 2 * t;
                uint32_t vh0 = LD32(bVh, rb), vh1 = LD32(bVh, rb + 8);
                uint32_t vl0 = LD32(bVl, rb), vl1 = LD32(bVl, rb + 8);
                mma_bf16(acc[j], ph[0], ph[1], ph[2], ph[3], vh0, vh1);
                mma_bf16(acc[j], ph[0], ph[1], ph[2], ph[3], vl0, vl1);
                mma_bf16(acc[j], pl[0], pl[1], pl[2], pl[3], vh0, vh1);
            }
        }
    }

    // write partial (unnormalized O, m, l)
    const int r0 = m0 + g;
    if (t == 0) {
        g_pm[(size_t)unit * 64 + r0] = mrow[0];
        g_pm[(size_t)unit * 64 + r0 + 8] = mrow[1];
        g_pl[(size_t)unit * 64 + r0] = lrow[0];
        g_pl[(size_t)unit * 64 + r0 + 8] = lrow[1];
    }
    #pragma unroll
    for (int j = 0; j < 8; ++j) {
        int col = 8 * j + 2 * t;
        size_t pbase = ((size_t)unit * 64 + r0) * HS + col;
        *(float2*)&g_po[pbase] = make_float2(acc[j][0], acc[j][1]);
        *(float2*)&g_po[pbase + 8 * HS] = make_float2(acc[j][2], acc[j][3]);
    }
}

// ---------------------------------------------------------------------------
// Combine partials: out = (sum_c w_c O_c) / (sum_c w_c l_c), w_c = 2^((m_c-m*)C)
// ---------------------------------------------------------------------------
__global__ __launch_bounds__(128) void reduce_kernel(float* __restrict__ out) {
    const int mb = blockIdx.x, b = blockIdx.y;
    const int nc = (mb >> 4) + 1;
    const int tid = threadIdx.x;
    const int r = tid >> 1, half = (tid & 1) * 32;
    const size_t ubase = ((size_t)(b * 64 + mb)) * NCHUNK;

    float m[NCHUNK], wgt[NCHUNK];
    float mstar = -1e30f;
    for (int c = 0; c < nc; ++c) {
        m[c] = g_pm[(ubase + c) * 64 + r];
        mstar = fmaxf(mstar, m[c]);
    }
    float lsum = 0.f;
    for (int c = 0; c < nc; ++c) {
        wgt[c] = exp2f((m[c] - mstar) * CSC);
        lsum += wgt[c] * g_pl[(ubase + c) * 64 + r];
    }
    float inv = 1.f / lsum;

    size_t orow = ((size_t)b * T_DIM + mb * 64 + r) * HS + half;
    #pragma unroll
    for (int j = 0; j < 8; ++j) {
        float4 o = make_float4(0.f, 0.f, 0.f, 0.f);
        for (int c = 0; c < nc; ++c) {
            const float4 p = *(const float4*)&g_po[((ubase + c) * 64 + r) * HS + half + j * 4];
            o.x += wgt[c] * p.x;
            o.y += wgt[c] * p.y;
            o.z += wgt[c] * p.z;
            o.w += wgt[c] * p.w;
        }
        *(float4*)&out[orow + j * 4] =
            make_float4(o.x * inv, o.y * inv, o.z * inv, o.w * inv);
    }
}

extern "C" void kernel_launch(void* const* d_in, const int* in_sizes, int n_in,
                              void* d_out, int out_size) {
    const float* x = (const float*)d_in[0];
    const float* Wk = (const float*)d_in[1];
    const float* Wv = (const float*)d_in[2];
    float* out = (float*)d_out;

    const int smemProj = 6 * 64 * PB * sizeof(uint16_t);  // 55296
    const int smemAttn = 2 * BUFBYTES;                    // 73728
    cudaFuncSetAttribute(proj_kernel, cudaFuncAttributeMaxDynamicSharedMemorySize, smemProj);
    cudaFuncSetAttribute(attn_kernel, cudaFuncAttributeMaxDynamicSharedMemorySize, smemAttn);

    wconv_kernel<<<HS * D_DIM / 512, 256>>>(Wk, Wv);
    proj_kernel<<<(B_DIM * T_DIM) / 64, 128, smemProj>>>(x);
    attn_kernel<<<dim3(64, NCHUNK, B_DIM), 128, smemAttn>>>();
    reduce_kernel<<<dim3(64, B_DIM), 128>>>(out);
}

// round 6
// speedup vs baseline: 7.2409x; 1.3188x over previous
#include <cuda_runtime.h>
#include <cuda_fp16.h>
#include <cstdint>

#define B_DIM 4
#define T_DIM 4096
#define D_DIM 1024
#define HS 64
#define PB 72      // fp16 pitch: conflict-free frag loads, 16B-aligned rows
#define NCHUNK 4   // max kv chunks per 64-row q-block
#define CBLK 16    // kv blocks (of 64 keys) per chunk

// Projected tensors (fp16). K: hi only. QV: hi/lo. QV^T: hi/lo.
__device__ __align__(16) uint16_t g_kh[B_DIM * T_DIM * HS];
__device__ __align__(16) uint16_t g_qh[B_DIM * T_DIM * HS];
__device__ __align__(16) uint16_t g_ql[B_DIM * T_DIM * HS];
__device__ __align__(16) uint16_t g_vth[B_DIM * HS * T_DIM];  // QV^T [b][h][t]
__device__ __align__(16) uint16_t g_vtl[B_DIM * HS * T_DIM];

// Preconverted weights: Wk hi; Wv hi/lo
__device__ __align__(16) uint16_t g_wkh[HS * D_DIM];
__device__ __align__(16) uint16_t g_wvh[HS * D_DIM];
__device__ __align__(16) uint16_t g_wvl[HS * D_DIM];

// Split-KV partials
__device__ float g_po[B_DIM * 64 * NCHUNK * 64 * HS];
__device__ float g_pm[B_DIM * 64 * NCHUNK * 64];
__device__ float g_pl[B_DIM * 64 * NCHUNK * 64];

#define CSC 0.1803368801111204f  // 0.125 * log2(e)

__device__ __forceinline__ uint32_t hpack(float a, float b) {
    __half2 hh = __floats2half2_rn(a, b);
    return *(uint32_t*)&hh;
}
__device__ __forceinline__ void packpair(float a, float b, uint32_t& h, uint32_t& l) {
    __half2 hh = __floats2half2_rn(a, b);
    h = *(uint32_t*)&hh;
    float2 fb = __half22float2(hh);
    l = hpack(a - fb.x, b - fb.y);
}
__device__ __forceinline__ void mma_f16(float* c, uint32_t a0, uint32_t a1,
                                        uint32_t a2, uint32_t a3,
                                        uint32_t b0, uint32_t b1) {
    asm volatile(
        "mma.sync.aligned.m16n8k16.row.col.f32.f16.f16.f32 "
        "{%0,%1,%2,%3}, {%4,%5,%6,%7}, {%8,%9}, {%0,%1,%2,%3};"
        : "+f"(c[0]), "+f"(c[1]), "+f"(c[2]), "+f"(c[3])
        : "r"(a0), "r"(a1), "r"(a2), "r"(a3), "r"(b0), "r"(b1));
}
__device__ __forceinline__ void sstore2(uint16_t* Sh, uint16_t* Sl, int off,
                                        float a, float b) {
    uint32_t h, l;
    packpair(a, b, h, l);
    *(uint32_t*)&Sh[off] = h;
    *(uint32_t*)&Sl[off] = l;
}
__device__ __forceinline__ void cpa16(uint32_t dst, const void* src) {
    asm volatile("cp.async.cg.shared.global [%0], [%1], 16;" :: "r"(dst), "l"(src));
}
#define LD32(arr, idx) (*(const uint32_t*)&(arr)[idx])

// ---------------------------------------------------------------------------
// One-time weight conversion fp32 -> fp16 (Wk hi; Wv hi/lo)
// ---------------------------------------------------------------------------
__global__ __launch_bounds__(256) void wconv_kernel(const float* __restrict__ Wk,
                                                    const float* __restrict__ Wv) {
    int i = blockIdx.x * 512 + threadIdx.x * 2;
    *(uint32_t*)&g_wkh[i] = hpack(Wk[i], Wk[i + 1]);
    uint32_t h, l;
    packpair(Wv[i], Wv[i + 1], h, l);
    *(uint32_t*)&g_wvh[i] = h;
    *(uint32_t*)&g_wvl[i] = l;
}

// ---------------------------------------------------------------------------
// Projection: k = x@Wk^T (2-MMA), qv = x@Wv^T (3-MMA). W via cp.async.
// ---------------------------------------------------------------------------
__global__ __launch_bounds__(128, 3) void proj_kernel(const float* __restrict__ x) {
    extern __shared__ __align__(16) uint16_t sm[];
    uint16_t* sXh = sm;
    uint16_t* sXl = sXh + 64 * PB;
    uint16_t* sWk = sXl + 64 * PB;
    uint16_t* sWvh = sWk + 64 * PB;
    uint16_t* sWvl = sWvh + 64 * PB;
    const uint32_t smb = (uint32_t)__cvta_generic_to_shared(sm);
    const uint32_t AB = 64 * PB * 2;

    const int tid = threadIdx.x;
    const int w = tid >> 5, lane = tid & 31, g = lane >> 2, t = lane & 3;
    const int RB = blockIdx.x * 64;
    const int m0 = w * 16;

    float accK[8][4] = {};
    float accV[8][4] = {};

    for (int d0 = 0; d0 < D_DIM; d0 += 64) {
        __syncthreads();
        // W tiles via cp.async (3 arrays x 512 16B-chunks)
        #pragma unroll
        for (int l = 0; l < 4; ++l) {
            int id = tid + l * 128;
            int r = id >> 3, c8 = (id & 7) * 8;
            uint32_t soff = (uint32_t)(r * PB + c8) * 2;
            size_t go = (size_t)r * D_DIM + d0 + c8;
            cpa16(smb + 2 * AB + soff, &g_wkh[go]);
            cpa16(smb + 3 * AB + soff, &g_wvh[go]);
            cpa16(smb + 4 * AB + soff, &g_wvl[go]);
        }
        asm volatile("cp.async.commit_group;");
        // x tile: fp32 -> fp16 hi/lo
        #pragma unroll
        for (int l = 0; l < 8; ++l) {
            int idx = tid + l * 128;
            int r = idx >> 4, c = (idx & 15) * 4;
            float4 fx = *(const float4*)&x[(size_t)(RB + r) * D_DIM + d0 + c];
            sstore2(sXh, sXl, r * PB + c, fx.x, fx.y);
            sstore2(sXh, sXl, r * PB + c + 2, fx.z, fx.w);
        }
        asm volatile("cp.async.wait_group 0;" ::: "memory");
        __syncthreads();

        #pragma unroll
        for (int k0 = 0; k0 < 64; k0 += 16) {
            int ra = (m0 + g) * PB + k0 + 2 * t;
            uint32_t ah0 = LD32(sXh, ra);
            uint32_t ah1 = LD32(sXh, ra + 8 * PB);
            uint32_t ah2 = LD32(sXh, ra + 8);
            uint32_t ah3 = LD32(sXh, ra + 8 * PB + 8);
            uint32_t al0 = LD32(sXl, ra);
            uint32_t al1 = LD32(sXl, ra + 8 * PB);
            uint32_t al2 = LD32(sXl, ra + 8);
            uint32_t al3 = LD32(sXl, ra + 8 * PB + 8);
            #pragma unroll
            for (int j = 0; j < 8; ++j) {
                int rb = (8 * j + g) * PB + k0 + 2 * t;
                uint32_t k0r = LD32(sWk, rb), k1r = LD32(sWk, rb + 8);
                mma_f16(accK[j], ah0, ah1, ah2, ah3, k0r, k1r);
                mma_f16(accK[j], al0, al1, al2, al3, k0r, k1r);
                uint32_t vh0 = LD32(sWvh, rb), vh1 = LD32(sWvh, rb + 8);
                uint32_t vl0 = LD32(sWvl, rb), vl1 = LD32(sWvl, rb + 8);
                mma_f16(accV[j], ah0, ah1, ah2, ah3, vh0, vh1);
                mma_f16(accV[j], ah0, ah1, ah2, ah3, vl0, vl1);
                mma_f16(accV[j], al0, al1, al2, al3, vh0, vh1);
            }
        }
    }

    const int row0 = RB + m0 + g;
    const int batch = row0 / T_DIM;
    const int tl0 = row0 % T_DIM;

    #pragma unroll
    for (int j = 0; j < 8; ++j) {
        int col = 8 * j + 2 * t;
        // K: hi only
        *(uint32_t*)&g_kh[(size_t)row0 * HS + col] = hpack(accK[j][0], accK[j][1]);
        *(uint32_t*)&g_kh[(size_t)(row0 + 8) * HS + col] = hpack(accK[j][2], accK[j][3]);
        // QV: hi/lo
        uint32_t h, l;
        packpair(accV[j][0], accV[j][1], h, l);
        *(uint32_t*)&g_qh[(size_t)row0 * HS + col] = h;
        *(uint32_t*)&g_ql[(size_t)row0 * HS + col] = l;
        packpair(accV[j][2], accV[j][3], h, l);
        *(uint32_t*)&g_qh[(size_t)(row0 + 8) * HS + col] = h;
        *(uint32_t*)&g_ql[(size_t)(row0 + 8) * HS + col] = l;
        // QV^T hi/lo, scalar scattered
        #pragma unroll
        for (int q = 0; q < 4; ++q) {
            float v = accV[j][q];
            int cc = col + (q & 1);
            int tt = tl0 + (q >> 1) * 8;
            __half hv = __float2half_rn(v);
            __half lv = __float2half_rn(v - __half2float(hv));
            size_t off = ((size_t)batch * HS + cc) * T_DIM + tt;
            g_vth[off] = *(uint16_t*)&hv;
            g_vtl[off] = *(uint16_t*)&lv;
        }
    }
}

// ---------------------------------------------------------------------------
// Split-KV flash attention. Buffers: Kh, Vth, Vtl (fp16).
// ---------------------------------------------------------------------------
#define ABYTES (64 * PB * 2)
#define BUFBYTES (3 * ABYTES)
#define AU16 (64 * PB)

__global__ __launch_bounds__(128, 3) void attn_kernel() {
    const int mblk = 63 - blockIdx.x;
    const int kb0 = blockIdx.y * CBLK;
    if (kb0 > mblk) return;
    const int kb1 = min(kb0 + CBLK - 1, mblk);
    const int b = blockIdx.z;
    const int unit = ((b * 64 + mblk) * NCHUNK) + blockIdx.y;

    extern __shared__ __align__(16) uint16_t sm[];
    const uint32_t smb = (uint32_t)__cvta_generic_to_shared(sm);

    const int tid = threadIdx.x;
    const int w = tid >> 5, lane = tid & 31, g = lane >> 2, t = lane & 3;
    const int qRow = mblk * 64;
    const int m0 = w * 16;
    const int lr = tid >> 3;
    const int lc = (tid & 7) * 8;

    // Q A-fragments (hi/lo) from global
    uint32_t qh[4][4], ql[4][4];
    {
        const uint16_t* Qh = g_qh + (size_t)b * T_DIM * HS;
        const uint16_t* Ql = g_ql + (size_t)b * T_DIM * HS;
        int base = (qRow + m0 + g) * HS + 2 * t;
        #pragma unroll
        for (int kk = 0; kk < 4; ++kk) {
            int o = base + kk * 16;
            qh[kk][0] = LD32(Qh, o);
            qh[kk][1] = LD32(Qh, o + 8 * HS);
            qh[kk][2] = LD32(Qh, o + 8);
            qh[kk][3] = LD32(Qh, o + 8 * HS + 8);
            ql[kk][0] = LD32(Ql, o);
            ql[kk][1] = LD32(Ql, o + 8 * HS);
            ql[kk][2] = LD32(Ql, o + 8);
            ql[kk][3] = LD32(Ql, o + 8 * HS + 8);
        }
    }

    auto issue_tile = [&](int buf, int kb) {
        uint32_t base = smb + buf * BUFBYTES;
        #pragma unroll
        for (int l = 0; l < 4; ++l) {
            int r = lr + l * 16;
            uint32_t soff = (uint32_t)(r * PB + lc) * 2;
            size_t gk = ((size_t)b * T_DIM + kb * 64 + r) * HS + lc;
            cpa16(base + soff, &g_kh[gk]);
            size_t gv = ((size_t)b * HS + r) * T_DIM + kb * 64 + lc;
            cpa16(base + ABYTES + soff, &g_vth[gv]);
            cpa16(base + 2 * ABYTES + soff, &g_vtl[gv]);
        }
        asm volatile("cp.async.commit_group;");
    };

    issue_tile(kb0 & 1, kb0);

    float acc[8][4] = {};
    float mrow[2] = {-1e30f, -1e30f};
    float lrow[2] = {0.f, 0.f};

    for (int kb = kb0; kb <= kb1; ++kb) {
        asm volatile("cp.async.wait_group 0;" ::: "memory");
        __syncthreads();
        if (kb < kb1) issue_tile((kb + 1) & 1, kb + 1);

        const uint16_t* bKh = sm + (kb & 1) * 3 * AU16;
        const uint16_t* bVh = bKh + AU16;
        const uint16_t* bVl = bKh + 2 * AU16;

        // S = Q @ K^T  (Q split, K single)
        float s[8][4] = {};
        #pragma unroll
        for (int kk = 0; kk < 4; ++kk) {
            #pragma unroll
            for (int j = 0; j < 8; ++j) {
                int rb = (8 * j + g) * PB + kk * 16 + 2 * t;
                uint32_t b0 = LD32(bKh, rb), b1 = LD32(bKh, rb + 8);
                mma_f16(s[j], qh[kk][0], qh[kk][1], qh[kk][2], qh[kk][3], b0, b1);
                mma_f16(s[j], ql[kk][0], ql[kk][1], ql[kk][2], ql[kk][3], b0, b1);
            }
        }

        // causal mask (diag block only); raw scores, scale folded into exp
        if (kb == mblk) {
            const int r0 = m0 + g, r1 = r0 + 8;
            #pragma unroll
            for (int j = 0; j < 8; ++j) {
                int c0 = 8 * j + 2 * t, c1 = c0 + 1;
                if (c0 > r0) s[j][0] = -1e30f;
                if (c1 > r0) s[j][1] = -1e30f;
                if (c0 > r1) s[j][2] = -1e30f;
                if (c1 > r1) s[j][3] = -1e30f;
            }
        }

        float mx0 = -1e30f, mx1 = -1e30f;
        #pragma unroll
        for (int j = 0; j < 8; ++j) {
            mx0 = fmaxf(mx0, fmaxf(s[j][0], s[j][1]));
            mx1 = fmaxf(mx1, fmaxf(s[j][2], s[j][3]));
        }
        mx0 = fmaxf(mx0, __shfl_xor_sync(0xffffffffu, mx0, 1));
        mx0 = fmaxf(mx0, __shfl_xor_sync(0xffffffffu, mx0, 2));
        mx1 = fmaxf(mx1, __shfl_xor_sync(0xffffffffu, mx1, 1));
        mx1 = fmaxf(mx1, __shfl_xor_sync(0xffffffffu, mx1, 2));
        float mn0 = fmaxf(mrow[0], mx0), mn1 = fmaxf(mrow[1], mx1);
        float cr0 = exp2f((mrow[0] - mn0) * CSC);
        float cr1 = exp2f((mrow[1] - mn1) * CSC);
        float sum0 = 0.f, sum1 = 0.f;
        #pragma unroll
        for (int j = 0; j < 8; ++j) {
            s[j][0] = exp2f((s[j][0] - mn0) * CSC);
            s[j][1] = exp2f((s[j][1] - mn0) * CSC);
            s[j][2] = exp2f((s[j][2] - mn1) * CSC);
            s[j][3] = exp2f((s[j][3] - mn1) * CSC);
            sum0 += s[j][0] + s[j][1];
            sum1 += s[j][2] + s[j][3];
        }
        sum0 += __shfl_xor_sync(0xffffffffu, sum0, 1);
        sum0 += __shfl_xor_sync(0xffffffffu, sum0, 2);
        sum1 += __shfl_xor_sync(0xffffffffu, sum1, 1);
        sum1 += __shfl_xor_sync(0xffffffffu, sum1, 2);
        lrow[0] = lrow[0] * cr0 + sum0;
        lrow[1] = lrow[1] * cr1 + sum1;
        mrow[0] = mn0;
        mrow[1] = mn1;
        #pragma unroll
        for (int j = 0; j < 8; ++j) {
            acc[j][0] *= cr0;
            acc[j][1] *= cr0;
            acc[j][2] *= cr1;
            acc[j][3] *= cr1;
        }

        // P split (regs) x V hi/lo: 3-MMA
        #pragma unroll
        for (int kk = 0; kk < 4; ++kk) {
            uint32_t ph[4], pl[4];
            float* pA = s[2 * kk];
            float* pB = s[2 * kk + 1];
            packpair(pA[0], pA[1], ph[0], pl[0]);
            packpair(pA[2], pA[3], ph[1], pl[1]);
            packpair(pB[0], pB[1], ph[2], pl[2]);
            packpair(pB[2], pB[3], ph[3], pl[3]);
            #pragma unroll
            for (int j = 0; j < 8; ++j) {
                int rb = (8 * j + g) * PB + kk * 16 + 2 * t;
                uint32_t vh0 = LD32(bVh, rb), vh1 = LD32(bVh, rb + 8);
                uint32_t vl0 = LD32(bVl, rb), vl1 = LD32(bVl, rb + 8);
                mma_f16(acc[j], ph[0], ph[1], ph[2], ph[3], vh0, vh1);
                mma_f16(acc[j], ph[0], ph[1], ph[2], ph[3], vl0, vl1);
                mma_f16(acc[j], pl[0], pl[1], pl[2], pl[3], vh0, vh1);
            }
        }
    }

    const int r0 = m0 + g;
    if (t == 0) {
        g_pm[(size_t)unit * 64 + r0] = mrow[0];
        g_pm[(size_t)unit * 64 + r0 + 8] = mrow[1];
        g_pl[(size_t)unit * 64 + r0] = lrow[0];
        g_pl[(size_t)unit * 64 + r0 + 8] = lrow[1];
    }
    #pragma unroll
    for (int j = 0; j < 8; ++j) {
        int col = 8 * j + 2 * t;
        size_t pbase = ((size_t)unit * 64 + r0) * HS + col;
        *(float2*)&g_po[pbase] = make_float2(acc[j][0], acc[j][1]);
        *(float2*)&g_po[pbase + 8 * HS] = make_float2(acc[j][2], acc[j][3]);
    }
}

// ---------------------------------------------------------------------------
// Combine partials. 256 thr: 4 threads per row, 16 cols each.
// ---------------------------------------------------------------------------
__global__ __launch_bounds__(256) void reduce_kernel(float* __restrict__ out) {
    const int mb = blockIdx.x, b = blockIdx.y;
    const int nc = (mb >> 4) + 1;
    const int tid = threadIdx.x;
    const int r = tid >> 2, q4 = (tid & 3) * 16;
    const size_t ubase = ((size_t)(b * 64 + mb)) * NCHUNK;

    float m[NCHUNK], wgt[NCHUNK];
    float mstar = -1e30f;
    for (int c = 0; c < nc; ++c) {
        m[c] = g_pm[(ubase + c) * 64 + r];
        mstar = fmaxf(mstar, m[c]);
    }
    float lsum = 0.f;
    for (int c = 0; c < nc; ++c) {
        wgt[c] = exp2f((m[c] - mstar) * CSC);
        lsum += wgt[c] * g_pl[(ubase + c) * 64 + r];
    }
    float inv = 1.f / lsum;

    size_t orow = ((size_t)b * T_DIM + mb * 64 + r) * HS + q4;
    #pragma unroll
    for (int j = 0; j < 4; ++j) {
        float4 o = make_float4(0.f, 0.f, 0.f, 0.f);
        for (int c = 0; c < nc; ++c) {
            const float4 p = *(const float4*)&g_po[((ubase + c) * 64 + r) * HS + q4 + j * 4];
            o.x += wgt[c] * p.x;
            o.y += wgt[c] * p.y;
            o.z += wgt[c] * p.z;
            o.w += wgt[c] * p.w;
        }
        *(float4*)&out[orow + j * 4] =
            make_float4(o.x * inv, o.y * inv, o.z * inv, o.w * inv);
    }
}

extern "C" void kernel_launch(void* const* d_in, const int* in_sizes, int n_in,
                              void* d_out, int out_size) {
    const float* x = (const float*)d_in[0];
    const float* Wk = (const float*)d_in[1];
    const float* Wv = (const float*)d_in[2];
    float* out = (float*)d_out;

    const int smemProj = 5 * 64 * PB * sizeof(uint16_t);  // 46080
    const int smemAttn = 2 * BUFBYTES;                    // 55296
    cudaFuncSetAttribute(proj_kernel, cudaFuncAttributeMaxDynamicSharedMemorySize, smemProj);
    cudaFuncSetAttribute(attn_kernel, cudaFuncAttributeMaxDynamicSharedMemorySize, smemAttn);

    wconv_kernel<<<HS * D_DIM / 512, 256>>>(Wk, Wv);
    proj_kernel<<<(B_DIM * T_DIM) / 64, 128, smemProj>>>(x);
    attn_kernel<<<dim3(64, NCHUNK, B_DIM), 128, smemAttn>>>();
    reduce_kernel<<<dim3(64, B_DIM), 256>>>(out);
}

// round 7
// speedup vs baseline: 8.3411x; 1.1519x over previous
#include <cuda_runtime.h>
#include <cuda_fp16.h>
#include <cstdint>

#define B_DIM 4
#define T_DIM 4096
#define D_DIM 1024
#define HS 64
#define PB 72      // fp16 pitch: conflict-free frag loads, 16B-aligned rows
#define NCHUNK 4   // max kv chunks per 64-row q-block
#define CBLK 16    // kv blocks (of 64 keys) per chunk

// Projected tensors (fp16). K: hi only. QV: hi/lo. QV^T: hi/lo.
__device__ __align__(16) uint16_t g_kh[B_DIM * T_DIM * HS];
__device__ __align__(16) uint16_t g_qh[B_DIM * T_DIM * HS];
__device__ __align__(16) uint16_t g_ql[B_DIM * T_DIM * HS];
__device__ __align__(16) uint16_t g_vth[B_DIM * HS * T_DIM];  // QV^T [b][h][t]
__device__ __align__(16) uint16_t g_vtl[B_DIM * HS * T_DIM];

// Preconverted weights: Wk hi; Wv hi/lo
__device__ __align__(16) uint16_t g_wkh[HS * D_DIM];
__device__ __align__(16) uint16_t g_wvh[HS * D_DIM];
__device__ __align__(16) uint16_t g_wvl[HS * D_DIM];

// Split-KV partials
__device__ float g_po[B_DIM * 64 * NCHUNK * 64 * HS];
__device__ float g_pm[B_DIM * 64 * NCHUNK * 64];
__device__ float g_pl[B_DIM * 64 * NCHUNK * 64];

#define CSC 0.1803368801111204f  // 0.125 * log2(e)

__device__ __forceinline__ uint32_t hpack(float a, float b) {
    __half2 hh = __floats2half2_rn(a, b);
    return *(uint32_t*)&hh;
}
__device__ __forceinline__ void packpair(float a, float b, uint32_t& h, uint32_t& l) {
    __half2 hh = __floats2half2_rn(a, b);
    h = *(uint32_t*)&hh;
    float2 fb = __half22float2(hh);
    l = hpack(a - fb.x, b - fb.y);
}
__device__ __forceinline__ void mma_f16(float* c, uint32_t a0, uint32_t a1,
                                        uint32_t a2, uint32_t a3,
                                        uint32_t b0, uint32_t b1) {
    asm volatile(
        "mma.sync.aligned.m16n8k16.row.col.f32.f16.f16.f32 "
        "{%0,%1,%2,%3}, {%4,%5,%6,%7}, {%8,%9}, {%0,%1,%2,%3};"
        : "+f"(c[0]), "+f"(c[1]), "+f"(c[2]), "+f"(c[3])
        : "r"(a0), "r"(a1), "r"(a2), "r"(a3), "r"(b0), "r"(b1));
}
__device__ __forceinline__ void sstore2(uint16_t* Sh, uint16_t* Sl, int off,
                                        float a, float b) {
    uint32_t h, l;
    packpair(a, b, h, l);
    *(uint32_t*)&Sh[off] = h;
    *(uint32_t*)&Sl[off] = l;
}
__device__ __forceinline__ void cpa16(uint32_t dst, const void* src) {
    asm volatile("cp.async.cg.shared.global [%0], [%1], 16;" :: "r"(dst), "l"(src));
}
#define LD32(arr, idx) (*(const uint32_t*)&(arr)[idx])

// ---------------------------------------------------------------------------
// One-time weight conversion fp32 -> fp16 (Wk hi; Wv hi/lo)
// ---------------------------------------------------------------------------
__global__ __launch_bounds__(256) void wconv_kernel(const float* __restrict__ Wk,
                                                    const float* __restrict__ Wv) {
    int i = blockIdx.x * 512 + threadIdx.x * 2;
    *(uint32_t*)&g_wkh[i] = hpack(Wk[i], Wk[i + 1]);
    uint32_t h, l;
    packpair(Wv[i], Wv[i + 1], h, l);
    *(uint32_t*)&g_wvh[i] = h;
    *(uint32_t*)&g_wvl[i] = l;
}

// ---------------------------------------------------------------------------
// Projection: k = x@Wk^T (1-MMA hi*hi), qv = x@Wv^T (3-MMA). W via cp.async.
// ---------------------------------------------------------------------------
__global__ __launch_bounds__(128, 3) void proj_kernel(const float* __restrict__ x) {
    extern __shared__ __align__(16) uint16_t sm[];
    uint16_t* sXh = sm;
    uint16_t* sXl = sXh + 64 * PB;
    uint16_t* sWk = sXl + 64 * PB;
    uint16_t* sWvh = sWk + 64 * PB;
    uint16_t* sWvl = sWvh + 64 * PB;
    const uint32_t smb = (uint32_t)__cvta_generic_to_shared(sm);
    const uint32_t AB = 64 * PB * 2;

    const int tid = threadIdx.x;
    const int w = tid >> 5, lane = tid & 31, g = lane >> 2, t = lane & 3;
    const int RB = blockIdx.x * 64;
    const int m0 = w * 16;

    float accK[8][4] = {};
    float accV[8][4] = {};

    for (int d0 = 0; d0 < D_DIM; d0 += 64) {
        __syncthreads();
        #pragma unroll
        for (int l = 0; l < 4; ++l) {
            int id = tid + l * 128;
            int r = id >> 3, c8 = (id & 7) * 8;
            uint32_t soff = (uint32_t)(r * PB + c8) * 2;
            size_t go = (size_t)r * D_DIM + d0 + c8;
            cpa16(smb + 2 * AB + soff, &g_wkh[go]);
            cpa16(smb + 3 * AB + soff, &g_wvh[go]);
            cpa16(smb + 4 * AB + soff, &g_wvl[go]);
        }
        asm volatile("cp.async.commit_group;");
        #pragma unroll
        for (int l = 0; l < 8; ++l) {
            int idx = tid + l * 128;
            int r = idx >> 4, c = (idx & 15) * 4;
            float4 fx = *(const float4*)&x[(size_t)(RB + r) * D_DIM + d0 + c];
            sstore2(sXh, sXl, r * PB + c, fx.x, fx.y);
            sstore2(sXh, sXl, r * PB + c + 2, fx.z, fx.w);
        }
        asm volatile("cp.async.wait_group 0;" ::: "memory");
        __syncthreads();

        #pragma unroll
        for (int k0 = 0; k0 < 64; k0 += 16) {
            int ra = (m0 + g) * PB + k0 + 2 * t;
            uint32_t ah0 = LD32(sXh, ra);
            uint32_t ah1 = LD32(sXh, ra + 8 * PB);
            uint32_t ah2 = LD32(sXh, ra + 8);
            uint32_t ah3 = LD32(sXh, ra + 8 * PB + 8);
            uint32_t al0 = LD32(sXl, ra);
            uint32_t al1 = LD32(sXl, ra + 8 * PB);
            uint32_t al2 = LD32(sXl, ra + 8);
            uint32_t al3 = LD32(sXl, ra + 8 * PB + 8);
            #pragma unroll
            for (int j = 0; j < 8; ++j) {
                int rb = (8 * j + g) * PB + k0 + 2 * t;
                uint32_t k0r = LD32(sWk, rb), k1r = LD32(sWk, rb + 8);
                mma_f16(accK[j], ah0, ah1, ah2, ah3, k0r, k1r);
                uint32_t vh0 = LD32(sWvh, rb), vh1 = LD32(sWvh, rb + 8);
                uint32_t vl0 = LD32(sWvl, rb), vl1 = LD32(sWvl, rb + 8);
                mma_f16(accV[j], ah0, ah1, ah2, ah3, vh0, vh1);
                mma_f16(accV[j], ah0, ah1, ah2, ah3, vl0, vl1);
                mma_f16(accV[j], al0, al1, al2, al3, vh0, vh1);
            }
        }
    }

    const int row0 = RB + m0 + g;
    const int batch = row0 / T_DIM;
    const int tl0 = row0 % T_DIM;

    #pragma unroll
    for (int j = 0; j < 8; ++j) {
        int col = 8 * j + 2 * t;
        *(uint32_t*)&g_kh[(size_t)row0 * HS + col] = hpack(accK[j][0], accK[j][1]);
        *(uint32_t*)&g_kh[(size_t)(row0 + 8) * HS + col] = hpack(accK[j][2], accK[j][3]);
        uint32_t h, l;
        packpair(accV[j][0], accV[j][1], h, l);
        *(uint32_t*)&g_qh[(size_t)row0 * HS + col] = h;
        *(uint32_t*)&g_ql[(size_t)row0 * HS + col] = l;
        packpair(accV[j][2], accV[j][3], h, l);
        *(uint32_t*)&g_qh[(size_t)(row0 + 8) * HS + col] = h;
        *(uint32_t*)&g_ql[(size_t)(row0 + 8) * HS + col] = l;
        #pragma unroll
        for (int q = 0; q < 4; ++q) {
            float v = accV[j][q];
            int cc = col + (q & 1);
            int tt = tl0 + (q >> 1) * 8;
            __half hv = __float2half_rn(v);
            __half lv = __float2half_rn(v - __half2float(hv));
            size_t off = ((size_t)batch * HS + cc) * T_DIM + tt;
            g_vth[off] = *(uint16_t*)&hv;
            g_vtl[off] = *(uint16_t*)&lv;
        }
    }
}

// ---------------------------------------------------------------------------
// Split-KV flash attention. Buffers: Kh, Vth, Vtl (fp16).
// ---------------------------------------------------------------------------
#define ABYTES (64 * PB * 2)
#define BUFBYTES (3 * ABYTES)
#define AU16 (64 * PB)

__global__ __launch_bounds__(128, 3) void attn_kernel() {
    const int mblk = 63 - blockIdx.x;
    const int kb0 = blockIdx.y * CBLK;
    if (kb0 > mblk) return;
    const int kb1 = min(kb0 + CBLK - 1, mblk);
    const int b = blockIdx.z;
    const int unit = ((b * 64 + mblk) * NCHUNK) + blockIdx.y;

    extern __shared__ __align__(16) uint16_t sm[];
    const uint32_t smb = (uint32_t)__cvta_generic_to_shared(sm);

    const int tid = threadIdx.x;
    const int w = tid >> 5, lane = tid & 31, g = lane >> 2, t = lane & 3;
    const int qRow = mblk * 64;
    const int m0 = w * 16;
    const int lr = tid >> 3;
    const int lc = (tid & 7) * 8;

    uint32_t qh[4][4], ql[4][4];
    {
        const uint16_t* Qh = g_qh + (size_t)b * T_DIM * HS;
        const uint16_t* Ql = g_ql + (size_t)b * T_DIM * HS;
        int base = (qRow + m0 + g) * HS + 2 * t;
        #pragma unroll
        for (int kk = 0; kk < 4; ++kk) {
            int o = base + kk * 16;
            qh[kk][0] = LD32(Qh, o);
            qh[kk][1] = LD32(Qh, o + 8 * HS);
            qh[kk][2] = LD32(Qh, o + 8);
            qh[kk][3] = LD32(Qh, o + 8 * HS + 8);
            ql[kk][0] = LD32(Ql, o);
            ql[kk][1] = LD32(Ql, o + 8 * HS);
            ql[kk][2] = LD32(Ql, o + 8);
            ql[kk][3] = LD32(Ql, o + 8 * HS + 8);
        }
    }

    auto issue_tile = [&](int buf, int kb) {
        uint32_t base = smb + buf * BUFBYTES;
        #pragma unroll
        for (int l = 0; l < 4; ++l) {
            int r = lr + l * 16;
            uint32_t soff = (uint32_t)(r * PB + lc) * 2;
            size_t gk = ((size_t)b * T_DIM + kb * 64 + r) * HS + lc;
            cpa16(base + soff, &g_kh[gk]);
            size_t gv = ((size_t)b * HS + r) * T_DIM + kb * 64 + lc;
            cpa16(base + ABYTES + soff, &g_vth[gv]);
            cpa16(base + 2 * ABYTES + soff, &g_vtl[gv]);
        }
        asm volatile("cp.async.commit_group;");
    };

    issue_tile(kb0 & 1, kb0);

    float acc[8][4] = {};
    float mrow[2] = {-1e30f, -1e30f};
    float lrow[2] = {0.f, 0.f};

    for (int kb = kb0; kb <= kb1; ++kb) {
        asm volatile("cp.async.wait_group 0;" ::: "memory");
        __syncthreads();
        if (kb < kb1) issue_tile((kb + 1) & 1, kb + 1);

        const uint16_t* bKh = sm + (kb & 1) * 3 * AU16;
        const uint16_t* bVh = bKh + AU16;
        const uint16_t* bVl = bKh + 2 * AU16;

        // S = Q @ K^T  (Q hi/lo, K single)
        float s[8][4] = {};
        #pragma unroll
        for (int kk = 0; kk < 4; ++kk) {
            #pragma unroll
            for (int j = 0; j < 8; ++j) {
                int rb = (8 * j + g) * PB + kk * 16 + 2 * t;
                uint32_t b0 = LD32(bKh, rb), b1 = LD32(bKh, rb + 8);
                mma_f16(s[j], qh[kk][0], qh[kk][1], qh[kk][2], qh[kk][3], b0, b1);
                mma_f16(s[j], ql[kk][0], ql[kk][1], ql[kk][2], ql[kk][3], b0, b1);
            }
        }

        if (kb == mblk) {
            const int r0 = m0 + g, r1 = r0 + 8;
            #pragma unroll
            for (int j = 0; j < 8; ++j) {
                int c0 = 8 * j + 2 * t, c1 = c0 + 1;
                if (c0 > r0) s[j][0] = -1e30f;
                if (c1 > r0) s[j][1] = -1e30f;
                if (c0 > r1) s[j][2] = -1e30f;
                if (c1 > r1) s[j][3] = -1e30f;
            }
        }

        float mx0 = -1e30f, mx1 = -1e30f;
        #pragma unroll
        for (int j = 0; j < 8; ++j) {
            mx0 = fmaxf(mx0, fmaxf(s[j][0], s[j][1]));
            mx1 = fmaxf(mx1, fmaxf(s[j][2], s[j][3]));
        }
        mx0 = fmaxf(mx0, __shfl_xor_sync(0xffffffffu, mx0, 1));
        mx0 = fmaxf(mx0, __shfl_xor_sync(0xffffffffu, mx0, 2));
        mx1 = fmaxf(mx1, __shfl_xor_sync(0xffffffffu, mx1, 1));
        mx1 = fmaxf(mx1, __shfl_xor_sync(0xffffffffu, mx1, 2));
        float mn0 = fmaxf(mrow[0], mx0), mn1 = fmaxf(mrow[1], mx1);
        float cr0 = exp2f((mrow[0] - mn0) * CSC);
        float cr1 = exp2f((mrow[1] - mn1) * CSC);
        float sum0 = 0.f, sum1 = 0.f;
        #pragma unroll
        for (int j = 0; j < 8; ++j) {
            s[j][0] = exp2f((s[j][0] - mn0) * CSC);
            s[j][1] = exp2f((s[j][1] - mn0) * CSC);
            s[j][2] = exp2f((s[j][2] - mn1) * CSC);
            s[j][3] = exp2f((s[j][3] - mn1) * CSC);
            sum0 += s[j][0] + s[j][1];
            sum1 += s[j][2] + s[j][3];
        }
        sum0 += __shfl_xor_sync(0xffffffffu, sum0, 1);
        sum0 += __shfl_xor_sync(0xffffffffu, sum0, 2);
        sum1 += __shfl_xor_sync(0xffffffffu, sum1, 1);
        sum1 += __shfl_xor_sync(0xffffffffu, sum1, 2);
        lrow[0] = lrow[0] * cr0 + sum0;
        lrow[1] = lrow[1] * cr1 + sum1;
        mrow[0] = mn0;
        mrow[1] = mn1;
        #pragma unroll
        for (int j = 0; j < 8; ++j) {
            acc[j][0] *= cr0;
            acc[j][1] *= cr0;
            acc[j][2] *= cr1;
            acc[j][3] *= cr1;
        }

        // P (hi only) x V hi/lo: 2-MMA per step
        #pragma unroll
        for (int kk = 0; kk < 4; ++kk) {
            uint32_t ph[4];
            float* pA = s[2 * kk];
            float* pB = s[2 * kk + 1];
            ph[0] = hpack(pA[0], pA[1]);
            ph[1] = hpack(pA[2], pA[3]);
            ph[2] = hpack(pB[0], pB[1]);
            ph[3] = hpack(pB[2], pB[3]);
            #pragma unroll
            for (int j = 0; j < 8; ++j) {
                int rb = (8 * j + g) * PB + kk * 16 + 2 * t;
                uint32_t vh0 = LD32(bVh, rb), vh1 = LD32(bVh, rb + 8);
                uint32_t vl0 = LD32(bVl, rb), vl1 = LD32(bVl, rb + 8);
                mma_f16(acc[j], ph[0], ph[1], ph[2], ph[3], vh0, vh1);
                mma_f16(acc[j], ph[0], ph[1], ph[2], ph[3], vl0, vl1);
            }
        }
    }

    const int r0 = m0 + g;
    if (t == 0) {
        g_pm[(size_t)unit * 64 + r0] = mrow[0];
        g_pm[(size_t)unit * 64 + r0 + 8] = mrow[1];
        g_pl[(size_t)unit * 64 + r0] = lrow[0];
        g_pl[(size_t)unit * 64 + r0 + 8] = lrow[1];
    }
    #pragma unroll
    for (int j = 0; j < 8; ++j) {
        int col = 8 * j + 2 * t;
        size_t pbase = ((size_t)unit * 64 + r0) * HS + col;
        *(float2*)&g_po[pbase] = make_float2(acc[j][0], acc[j][1]);
        *(float2*)&g_po[pbase + 8 * HS] = make_float2(acc[j][2], acc[j][3]);
    }
}

// ---------------------------------------------------------------------------
// Combine partials. Grid (64, B, 4): blockIdx.z = 16-col quarter.
// ---------------------------------------------------------------------------
__global__ __launch_bounds__(256) void reduce_kernel(float* __restrict__ out) {
    const int mb = blockIdx.x, b = blockIdx.y;
    const int nc = (mb >> 4) + 1;
    const int tid = threadIdx.x;
    const int r = tid >> 2;
    const int col = blockIdx.z * 16 + (tid & 3) * 4;
    const size_t ubase = ((size_t)(b * 64 + mb)) * NCHUNK;

    float m[NCHUNK], wgt[NCHUNK];
    float mstar = -1e30f;
    #pragma unroll
    for (int c = 0; c < NCHUNK; ++c) {
        if (c < nc) {
            m[c] = g_pm[(ubase + c) * 64 + r];
            mstar = fmaxf(mstar, m[c]);
        }
    }
    float lsum = 0.f;
    #pragma unroll
    for (int c = 0; c < NCHUNK; ++c) {
        if (c < nc) {
            wgt[c] = exp2f((m[c] - mstar) * CSC);
            lsum += wgt[c] * g_pl[(ubase + c) * 64 + r];
        }
    }
    float inv = 1.f / lsum;

    float4 o = make_float4(0.f, 0.f, 0.f, 0.f);
    #pragma unroll
    for (int c = 0; c < NCHUNK; ++c) {
        if (c < nc) {
            const float4 p = *(const float4*)&g_po[((ubase + c) * 64 + r) * HS + col];
            o.x += wgt[c] * p.x;
            o.y += wgt[c] * p.y;
            o.z += wgt[c] * p.z;
            o.w += wgt[c] * p.w;
        }
    }
    *(float4*)&out[((size_t)b * T_DIM + mb * 64 + r) * HS + col] =
        make_float4(o.x * inv, o.y * inv, o.z * inv, o.w * inv);
}

extern "C" void kernel_launch(void* const* d_in, const int* in_sizes, int n_in,
                              void* d_out, int out_size) {
    const float* x = (const float*)d_in[0];
    const float* Wk = (const float*)d_in[1];
    const float* Wv = (const float*)d_in[2];
    float* out = (float*)d_out;

    const int smemProj = 5 * 64 * PB * sizeof(uint16_t);  // 46080
    const int smemAttn = 2 * BUFBYTES;                    // 55296
    cudaFuncSetAttribute(proj_kernel, cudaFuncAttributeMaxDynamicSharedMemorySize, smemProj);
    cudaFuncSetAttribute(attn_kernel, cudaFuncAttributeMaxDynamicSharedMemorySize, smemAttn);

    wconv_kernel<<<HS * D_DIM / 512, 256>>>(Wk, Wv);
    proj_kernel<<<(B_DIM * T_DIM) / 64, 128, smemProj>>>(x);
    attn_kernel<<<dim3(64, NCHUNK, B_DIM), 128, smemAttn>>>();
    reduce_kernel<<<dim3(64, B_DIM, 4), 256>>>(out);
}

// round 8
// speedup vs baseline: 10.2899x; 1.2336x over previous
#include <cuda_runtime.h>
#include <cuda_fp16.h>
#include <cstdint>

#define B_DIM 4
#define T_DIM 4096
#define D_DIM 1024
#define HS 64
#define PB 72      // fp16 pitch: conflict-free frag loads, 16B-aligned rows
#define QBLK 128   // q rows per attn CTA
#define NCHUNK 8   // max kv chunks per q-block
#define CBLK 8     // kv blocks (of 64 keys) per chunk

// Projected tensors (fp16). K: hi only. QV: hi/lo. QV^T: hi/lo.
__device__ __align__(16) uint16_t g_kh[B_DIM * T_DIM * HS];
__device__ __align__(16) uint16_t g_qh[B_DIM * T_DIM * HS];
__device__ __align__(16) uint16_t g_ql[B_DIM * T_DIM * HS];
__device__ __align__(16) uint16_t g_vth[B_DIM * HS * T_DIM];  // QV^T [b][h][t]
__device__ __align__(16) uint16_t g_vtl[B_DIM * HS * T_DIM];

// Preconverted weights: Wk hi; Wv hi/lo
__device__ __align__(16) uint16_t g_wkh[HS * D_DIM];
__device__ __align__(16) uint16_t g_wvh[HS * D_DIM];
__device__ __align__(16) uint16_t g_wvl[HS * D_DIM];

// Split-KV partials: unit = (b*32 + mblk)*NCHUNK + chunk, 128 rows each
__device__ float g_po[B_DIM * 32 * NCHUNK * QBLK * HS];
__device__ float g_pm[B_DIM * 32 * NCHUNK * QBLK];
__device__ float g_pl[B_DIM * 32 * NCHUNK * QBLK];

#define CSC 0.1803368801111204f  // 0.125 * log2(e)

__device__ __forceinline__ uint32_t hpack(float a, float b) {
    __half2 hh = __floats2half2_rn(a, b);
    return *(uint32_t*)&hh;
}
__device__ __forceinline__ void packpair(float a, float b, uint32_t& h, uint32_t& l) {
    __half2 hh = __floats2half2_rn(a, b);
    h = *(uint32_t*)&hh;
    float2 fb = __half22float2(hh);
    l = hpack(a - fb.x, b - fb.y);
}
__device__ __forceinline__ void mma_f16(float* c, uint32_t a0, uint32_t a1,
                                        uint32_t a2, uint32_t a3,
                                        uint32_t b0, uint32_t b1) {
    asm volatile(
        "mma.sync.aligned.m16n8k16.row.col.f32.f16.f16.f32 "
        "{%0,%1,%2,%3}, {%4,%5,%6,%7}, {%8,%9}, {%0,%1,%2,%3};"
        : "+f"(c[0]), "+f"(c[1]), "+f"(c[2]), "+f"(c[3])
        : "r"(a0), "r"(a1), "r"(a2), "r"(a3), "r"(b0), "r"(b1));
}
__device__ __forceinline__ void sstore2(uint16_t* Sh, uint16_t* Sl, int off,
                                        float a, float b) {
    uint32_t h, l;
    packpair(a, b, h, l);
    *(uint32_t*)&Sh[off] = h;
    *(uint32_t*)&Sl[off] = l;
}
__device__ __forceinline__ void cpa16(uint32_t dst, const void* src) {
    asm volatile("cp.async.cg.shared.global [%0], [%1], 16;" :: "r"(dst), "l"(src));
}
#define LD32(arr, idx) (*(const uint32_t*)&(arr)[idx])

// ---------------------------------------------------------------------------
// One-time weight conversion fp32 -> fp16 (Wk hi; Wv hi/lo)
// ---------------------------------------------------------------------------
__global__ __launch_bounds__(256) void wconv_kernel(const float* __restrict__ Wk,
                                                    const float* __restrict__ Wv) {
    int i = blockIdx.x * 512 + threadIdx.x * 2;
    *(uint32_t*)&g_wkh[i] = hpack(Wk[i], Wk[i + 1]);
    uint32_t h, l;
    packpair(Wv[i], Wv[i + 1], h, l);
    *(uint32_t*)&g_wvh[i] = h;
    *(uint32_t*)&g_wvl[i] = l;
}

// ---------------------------------------------------------------------------
// Projection: k = x@Wk^T (1-MMA), qv = x@Wv^T (3-MMA). W via cp.async.
// ---------------------------------------------------------------------------
__global__ __launch_bounds__(128, 3) void proj_kernel(const float* __restrict__ x) {
    extern __shared__ __align__(16) uint16_t sm[];
    uint16_t* sXh = sm;
    uint16_t* sXl = sXh + 64 * PB;
    uint16_t* sWk = sXl + 64 * PB;
    uint16_t* sWvh = sWk + 64 * PB;
    uint16_t* sWvl = sWvh + 64 * PB;
    const uint32_t smb = (uint32_t)__cvta_generic_to_shared(sm);
    const uint32_t AB = 64 * PB * 2;

    const int tid = threadIdx.x;
    const int w = tid >> 5, lane = tid & 31, g = lane >> 2, t = lane & 3;
    const int RB = blockIdx.x * 64;
    const int m0 = w * 16;

    float accK[8][4] = {};
    float accV[8][4] = {};

    for (int d0 = 0; d0 < D_DIM; d0 += 64) {
        __syncthreads();
        #pragma unroll
        for (int l = 0; l < 4; ++l) {
            int id = tid + l * 128;
            int r = id >> 3, c8 = (id & 7) * 8;
            uint32_t soff = (uint32_t)(r * PB + c8) * 2;
            size_t go = (size_t)r * D_DIM + d0 + c8;
            cpa16(smb + 2 * AB + soff, &g_wkh[go]);
            cpa16(smb + 3 * AB + soff, &g_wvh[go]);
            cpa16(smb + 4 * AB + soff, &g_wvl[go]);
        }
        asm volatile("cp.async.commit_group;");
        #pragma unroll
        for (int l = 0; l < 8; ++l) {
            int idx = tid + l * 128;
            int r = idx >> 4, c = (idx & 15) * 4;
            float4 fx = *(const float4*)&x[(size_t)(RB + r) * D_DIM + d0 + c];
            sstore2(sXh, sXl, r * PB + c, fx.x, fx.y);
            sstore2(sXh, sXl, r * PB + c + 2, fx.z, fx.w);
        }
        asm volatile("cp.async.wait_group 0;" ::: "memory");
        __syncthreads();

        #pragma unroll
        for (int k0 = 0; k0 < 64; k0 += 16) {
            int ra = (m0 + g) * PB + k0 + 2 * t;
            uint32_t ah0 = LD32(sXh, ra);
            uint32_t ah1 = LD32(sXh, ra + 8 * PB);
            uint32_t ah2 = LD32(sXh, ra + 8);
            uint32_t ah3 = LD32(sXh, ra + 8 * PB + 8);
            uint32_t al0 = LD32(sXl, ra);
            uint32_t al1 = LD32(sXl, ra + 8 * PB);
            uint32_t al2 = LD32(sXl, ra + 8);
            uint32_t al3 = LD32(sXl, ra + 8 * PB + 8);
            #pragma unroll
            for (int j = 0; j < 8; ++j) {
                int rb = (8 * j + g) * PB + k0 + 2 * t;
                uint32_t k0r = LD32(sWk, rb), k1r = LD32(sWk, rb + 8);
                mma_f16(accK[j], ah0, ah1, ah2, ah3, k0r, k1r);
                uint32_t vh0 = LD32(sWvh, rb), vh1 = LD32(sWvh, rb + 8);
                uint32_t vl0 = LD32(sWvl, rb), vl1 = LD32(sWvl, rb + 8);
                mma_f16(accV[j], ah0, ah1, ah2, ah3, vh0, vh1);
                mma_f16(accV[j], ah0, ah1, ah2, ah3, vl0, vl1);
                mma_f16(accV[j], al0, al1, al2, al3, vh0, vh1);
            }
        }
    }

    const int row0 = RB + m0 + g;
    const int batch = row0 / T_DIM;
    const int tl0 = row0 % T_DIM;

    #pragma unroll
    for (int j = 0; j < 8; ++j) {
        int col = 8 * j + 2 * t;
        *(uint32_t*)&g_kh[(size_t)row0 * HS + col] = hpack(accK[j][0], accK[j][1]);
        *(uint32_t*)&g_kh[(size_t)(row0 + 8) * HS + col] = hpack(accK[j][2], accK[j][3]);
        uint32_t h, l;
        packpair(accV[j][0], accV[j][1], h, l);
        *(uint32_t*)&g_qh[(size_t)row0 * HS + col] = h;
        *(uint32_t*)&g_ql[(size_t)row0 * HS + col] = l;
        packpair(accV[j][2], accV[j][3], h, l);
        *(uint32_t*)&g_qh[(size_t)(row0 + 8) * HS + col] = h;
        *(uint32_t*)&g_ql[(size_t)(row0 + 8) * HS + col] = l;
        #pragma unroll
        for (int q = 0; q < 4; ++q) {
            float v = accV[j][q];
            int cc = col + (q & 1);
            int tt = tl0 + (q >> 1) * 8;
            __half hv = __float2half_rn(v);
            __half lv = __float2half_rn(v - __half2float(hv));
            size_t off = ((size_t)batch * HS + cc) * T_DIM + tt;
            g_vth[off] = *(uint16_t*)&hv;
            g_vtl[off] = *(uint16_t*)&lv;
        }
    }
}

// ---------------------------------------------------------------------------
// Split-KV flash attention, QBLK=128 (warp: 32 rows as two 16-row A-tiles).
// ---------------------------------------------------------------------------
#define ABYTES (64 * PB * 2)
#define BUFBYTES (3 * ABYTES)
#define AU16 (64 * PB)

__global__ __launch_bounds__(128, 2) void attn_kernel() {
    const int mblk = 31 - blockIdx.x;          // longest-first
    const int kbLast = 2 * mblk + 1;
    const int kb0 = blockIdx.y * CBLK;
    if (kb0 > kbLast) return;
    const int kb1 = min(kb0 + CBLK - 1, kbLast);
    const int b = blockIdx.z;
    const int unit = (b * 32 + mblk) * NCHUNK + blockIdx.y;

    extern __shared__ __align__(16) uint16_t sm[];
    const uint32_t smb = (uint32_t)__cvta_generic_to_shared(sm);

    const int tid = threadIdx.x;
    const int w = tid >> 5, lane = tid & 31, g = lane >> 2, t = lane & 3;
    const int qRow = mblk * QBLK;
    const int m0 = w * 32;
    const int lr = tid >> 3;
    const int lc = (tid & 7) * 8;

    // Q A-fragments (single fp16), two row tiles
    uint32_t q[2][4][4];
    {
        const uint16_t* Qh = g_qh + (size_t)b * T_DIM * HS;
        #pragma unroll
        for (int tt = 0; tt < 2; ++tt) {
            int base = (qRow + m0 + tt * 16 + g) * HS + 2 * t;
            #pragma unroll
            for (int kk = 0; kk < 4; ++kk) {
                int o = base + kk * 16;
                q[tt][kk][0] = LD32(Qh, o);
                q[tt][kk][1] = LD32(Qh, o + 8 * HS);
                q[tt][kk][2] = LD32(Qh, o + 8);
                q[tt][kk][3] = LD32(Qh, o + 8 * HS + 8);
            }
        }
    }

    auto issue_tile = [&](int buf, int kb) {
        uint32_t base = smb + buf * BUFBYTES;
        #pragma unroll
        for (int l = 0; l < 4; ++l) {
            int r = lr + l * 16;
            uint32_t soff = (uint32_t)(r * PB + lc) * 2;
            size_t gk = ((size_t)b * T_DIM + kb * 64 + r) * HS + lc;
            cpa16(base + soff, &g_kh[gk]);
            size_t gv = ((size_t)b * HS + r) * T_DIM + kb * 64 + lc;
            cpa16(base + ABYTES + soff, &g_vth[gv]);
            cpa16(base + 2 * ABYTES + soff, &g_vtl[gv]);
        }
        asm volatile("cp.async.commit_group;");
    };

    issue_tile(kb0 & 1, kb0);

    float acc[2][8][4] = {};
    float mrow[4] = {-1e30f, -1e30f, -1e30f, -1e30f};
    float lrow[4] = {0.f, 0.f, 0.f, 0.f};

    for (int kb = kb0; kb <= kb1; ++kb) {
        asm volatile("cp.async.wait_group 0;" ::: "memory");
        __syncthreads();
        if (kb < kb1) issue_tile((kb + 1) & 1, kb + 1);

        const uint16_t* bKh = sm + (kb & 1) * 3 * AU16;
        const uint16_t* bVh = bKh + AU16;
        const uint16_t* bVl = bKh + 2 * AU16;

        // S = Q @ K^T for both row tiles
        float s[2][8][4] = {};
        #pragma unroll
        for (int kk = 0; kk < 4; ++kk) {
            #pragma unroll
            for (int j = 0; j < 8; ++j) {
                int rb = (8 * j + g) * PB + kk * 16 + 2 * t;
                uint32_t b0 = LD32(bKh, rb), b1 = LD32(bKh, rb + 8);
                mma_f16(s[0][j], q[0][kk][0], q[0][kk][1], q[0][kk][2], q[0][kk][3], b0, b1);
                mma_f16(s[1][j], q[1][kk][0], q[1][kk][1], q[1][kk][2], q[1][kk][3], b0, b1);
            }
        }

        // causal mask: only the last two kv blocks overlap the diagonal
        if (kb >= 2 * mblk) {
            const int off = qRow - kb * 64;  // 0 or -64
            #pragma unroll
            for (int tt = 0; tt < 2; ++tt) {
                int r0l = m0 + tt * 16 + g + off, r1l = r0l + 8;
                #pragma unroll
                for (int j = 0; j < 8; ++j) {
                    int c0 = 8 * j + 2 * t, c1 = c0 + 1;
                    if (c0 > r0l) s[tt][j][0] = -1e30f;
                    if (c1 > r0l) s[tt][j][1] = -1e30f;
                    if (c0 > r1l) s[tt][j][2] = -1e30f;
                    if (c1 > r1l) s[tt][j][3] = -1e30f;
                }
            }
        }

        // online softmax: 4 row groups (tile0:g,g+8; tile1:+16,+24)
        #pragma unroll
        for (int tt = 0; tt < 2; ++tt) {
            float mx0 = -1e30f, mx1 = -1e30f;
            #pragma unroll
            for (int j = 0; j < 8; ++j) {
                mx0 = fmaxf(mx0, fmaxf(s[tt][j][0], s[tt][j][1]));
                mx1 = fmaxf(mx1, fmaxf(s[tt][j][2], s[tt][j][3]));
            }
            mx0 = fmaxf(mx0, __shfl_xor_sync(0xffffffffu, mx0, 1));
            mx0 = fmaxf(mx0, __shfl_xor_sync(0xffffffffu, mx0, 2));
            mx1 = fmaxf(mx1, __shfl_xor_sync(0xffffffffu, mx1, 1));
            mx1 = fmaxf(mx1, __shfl_xor_sync(0xffffffffu, mx1, 2));
            float mn0 = fmaxf(mrow[tt * 2], mx0), mn1 = fmaxf(mrow[tt * 2 + 1], mx1);
            float cr0 = exp2f((mrow[tt * 2] - mn0) * CSC);
            float cr1 = exp2f((mrow[tt * 2 + 1] - mn1) * CSC);
            float sum0 = 0.f, sum1 = 0.f;
            #pragma unroll
            for (int j = 0; j < 8; ++j) {
                s[tt][j][0] = exp2f((s[tt][j][0] - mn0) * CSC);
                s[tt][j][1] = exp2f((s[tt][j][1] - mn0) * CSC);
                s[tt][j][2] = exp2f((s[tt][j][2] - mn1) * CSC);
                s[tt][j][3] = exp2f((s[tt][j][3] - mn1) * CSC);
                sum0 += s[tt][j][0] + s[tt][j][1];
                sum1 += s[tt][j][2] + s[tt][j][3];
            }
            sum0 += __shfl_xor_sync(0xffffffffu, sum0, 1);
            sum0 += __shfl_xor_sync(0xffffffffu, sum0, 2);
            sum1 += __shfl_xor_sync(0xffffffffu, sum1, 1);
            sum1 += __shfl_xor_sync(0xffffffffu, sum1, 2);
            lrow[tt * 2] = lrow[tt * 2] * cr0 + sum0;
            lrow[tt * 2 + 1] = lrow[tt * 2 + 1] * cr1 + sum1;
            mrow[tt * 2] = mn0;
            mrow[tt * 2 + 1] = mn1;
            #pragma unroll
            for (int j = 0; j < 8; ++j) {
                acc[tt][j][0] *= cr0;
                acc[tt][j][1] *= cr0;
                acc[tt][j][2] *= cr1;
                acc[tt][j][3] *= cr1;
            }
        }

        // P (hi only) x V hi/lo for both row tiles
        #pragma unroll
        for (int kk = 0; kk < 4; ++kk) {
            uint32_t ph[2][4];
            #pragma unroll
            for (int tt = 0; tt < 2; ++tt) {
                float* pA = s[tt][2 * kk];
                float* pB = s[tt][2 * kk + 1];
                ph[tt][0] = hpack(pA[0], pA[1]);
                ph[tt][1] = hpack(pA[2], pA[3]);
                ph[tt][2] = hpack(pB[0], pB[1]);
                ph[tt][3] = hpack(pB[2], pB[3]);
            }
            #pragma unroll
            for (int j = 0; j < 8; ++j) {
                int rb = (8 * j + g) * PB + kk * 16 + 2 * t;
                uint32_t vh0 = LD32(bVh, rb), vh1 = LD32(bVh, rb + 8);
                uint32_t vl0 = LD32(bVl, rb), vl1 = LD32(bVl, rb + 8);
                mma_f16(acc[0][j], ph[0][0], ph[0][1], ph[0][2], ph[0][3], vh0, vh1);
                mma_f16(acc[0][j], ph[0][0], ph[0][1], ph[0][2], ph[0][3], vl0, vl1);
                mma_f16(acc[1][j], ph[1][0], ph[1][1], ph[1][2], ph[1][3], vh0, vh1);
                mma_f16(acc[1][j], ph[1][0], ph[1][1], ph[1][2], ph[1][3], vl0, vl1);
            }
        }
    }

    // write partials
    if (t == 0) {
        #pragma unroll
        for (int tt = 0; tt < 2; ++tt) {
            int r = m0 + tt * 16 + g;
            g_pm[(size_t)unit * QBLK + r] = mrow[tt * 2];
            g_pm[(size_t)unit * QBLK + r + 8] = mrow[tt * 2 + 1];
            g_pl[(size_t)unit * QBLK + r] = lrow[tt * 2];
            g_pl[(size_t)unit * QBLK + r + 8] = lrow[tt * 2 + 1];
        }
    }
    #pragma unroll
    for (int tt = 0; tt < 2; ++tt) {
        int r = m0 + tt * 16 + g;
        #pragma unroll
        for (int j = 0; j < 8; ++j) {
            int col = 8 * j + 2 * t;
            size_t pbase = ((size_t)unit * QBLK + r) * HS + col;
            *(float2*)&g_po[pbase] = make_float2(acc[tt][j][0], acc[tt][j][1]);
            *(float2*)&g_po[pbase + 8 * HS] = make_float2(acc[tt][j][2], acc[tt][j][3]);
        }
    }
}

// ---------------------------------------------------------------------------
// Combine partials. Grid (32, B, 8): blockIdx.z = 8-col octet. 256 thr.
// ---------------------------------------------------------------------------
__global__ __launch_bounds__(256) void reduce_kernel(float* __restrict__ out) {
    const int mb = blockIdx.x, b = blockIdx.y;
    const int nc = (2 * mb + 2 + CBLK - 1) / CBLK;
    const int tid = threadIdx.x;
    const int r = tid >> 1;
    const int col = blockIdx.z * 8 + (tid & 1) * 4;
    const size_t ubase = ((size_t)(b * 32 + mb)) * NCHUNK;

    float m[NCHUNK], wgt[NCHUNK];
    float mstar = -1e30f;
    #pragma unroll
    for (int c = 0; c < NCHUNK; ++c) {
        if (c < nc) {
            m[c] = g_pm[(ubase + c) * QBLK + r];
            mstar = fmaxf(mstar, m[c]);
        }
    }
    float lsum = 0.f;
    #pragma unroll
    for (int c = 0; c < NCHUNK; ++c) {
        if (c < nc) {
            wgt[c] = exp2f((m[c] - mstar) * CSC);
            lsum += wgt[c] * g_pl[(ubase + c) * QBLK + r];
        }
    }
    float inv = 1.f / lsum;

    float4 o = make_float4(0.f, 0.f, 0.f, 0.f);
    #pragma unroll
    for (int c = 0; c < NCHUNK; ++c) {
        if (c < nc) {
            const float4 p = *(const float4*)&g_po[((ubase + c) * QBLK + r) * HS + col];
            o.x += wgt[c] * p.x;
            o.y += wgt[c] * p.y;
            o.z += wgt[c] * p.z;
            o.w += wgt[c] * p.w;
        }
    }
    *(float4*)&out[((size_t)b * T_DIM + mb * QBLK + r) * HS + col] =
        make_float4(o.x * inv, o.y * inv, o.z * inv, o.w * inv);
}

extern "C" void kernel_launch(void* const* d_in, const int* in_sizes, int n_in,
                              void* d_out, int out_size) {
    const float* x = (const float*)d_in[0];
    const float* Wk = (const float*)d_in[1];
    const float* Wv = (const float*)d_in[2];
    float* out = (float*)d_out;

    const int smemProj = 5 * 64 * PB * sizeof(uint16_t);  // 46080
    const int smemAttn = 2 * BUFBYTES;                    // 55296
    cudaFuncSetAttribute(proj_kernel, cudaFuncAttributeMaxDynamicSharedMemorySize, smemProj);
    cudaFuncSetAttribute(attn_kernel, cudaFuncAttributeMaxDynamicSharedMemorySize, smemAttn);

    wconv_kernel<<<HS * D_DIM / 512, 256>>>(Wk, Wv);
    proj_kernel<<<(B_DIM * T_DIM) / 64, 128, smemProj>>>(x);
    attn_kernel<<<dim3(32, NCHUNK, B_DIM), 128, smemAttn>>>();
    reduce_kernel<<<dim3(32, B_DIM, 8), 256>>>(out);
}